// round 2
// baseline (speedup 1.0000x reference)
#include <cuda_runtime.h>
#include <stdint.h>

#define B_    4
#define S_    2048
#define E_    1024
#define QKV_LD 3072
#define NTILE ((S_/2)*(E_/2))   // 524288 tiles per (b, q|k)
#define NSEL  12                // 0..3 q-batches, 4..7 k-batches, 8..11 WO-batches

// ---------------- scratch (device globals: no allocations allowed) ----------
__device__ float g_qkv[B_*S_*QKV_LD];          // 96 MB  [b, s, 3E] (q|k|v)
__device__ float g_norm_q[B_*NTILE];           // 8 MB
__device__ float g_norm_k[B_*NTILE];           // 8 MB
__device__ float g_norm_wo[B_*S_];
__device__ float g_wmask[B_*S_];
__device__ float g_Amat[B_*E_*E_];             // Qp^T Kp
__device__ float g_H1[B_*E_*E_];               // x^T v
__device__ float g_G [B_*E_*E_];               // WO_^T x
__device__ float g_T [B_*E_*E_];               // H1 G
__device__ float g_U [B_*E_*E_];               // A T / 32

__device__ unsigned g_hist[NSEL][256];
__device__ unsigned g_prefix[NSEL];
__device__ int      g_kk[NSEL];
__device__ unsigned g_cntless[NSEL];
__device__ unsigned g_maxbelow[NSEL];
__device__ float    g_thr[NSEL];

__device__ __forceinline__ void sel_info(int sel, const float** p, int* n) {
    if (sel < 4)      { *p = g_norm_q  + (size_t)sel * NTILE;       *n = NTILE; }
    else if (sel < 8) { *p = g_norm_k  + (size_t)(sel-4) * NTILE;   *n = NTILE; }
    else              { *p = g_norm_wo + (size_t)(sel-8) * S_;      *n = S_;    }
}

// ---------------- SGEMM: 128x128 tile, BK=16, 8x8 per thread ----------------
// MODE 0 = NT: C[M,N] = A[M,K] * B[N,K]^T   (+bias per column)
// MODE 1 = TN: C[M,N] = A[K,M]^T * B[K,N]   (optional per-k-row mask on A)
// MODE 2 = NN: C[M,N] = A[M,K] * B[K,N]
// Two-level accumulation: per-BK-slice partial t[8][8] folded into s[8][8]
// once per slice -> accumulation error drops ~10-15x vs sequential-K.
#define BM 128
#define BN 128
#define BKK 16

template<int MODE>
__global__ void __launch_bounds__(256, 1) sgemm_k(
    const float* __restrict__ A, int lda, size_t sA,
    const float* __restrict__ B, int ldb, size_t sB,
    float* __restrict__ C, int ldc, size_t sC,
    int M, int N, int K,
    const float* __restrict__ bias,
    const float* __restrict__ rmask, size_t sMask,
    float alpha)
{
    __shared__ float As[BKK][BM];
    __shared__ float Bs[BKK][BN];
    const int bz = blockIdx.z;
    A += (size_t)bz * sA;  B += (size_t)bz * sB;  C += (size_t)bz * sC;
    const float* rm = rmask ? (rmask + (size_t)bz * sMask) : nullptr;
    const int bm = blockIdx.y * BM, bn = blockIdx.x * BN;
    const int tid = threadIdx.x;
    const int tx = tid & 15, ty = tid >> 4;

    float s[8][8];
    #pragma unroll
    for (int i = 0; i < 8; i++)
        #pragma unroll
        for (int j = 0; j < 8; j++) s[i][j] = 0.f;

    for (int k0 = 0; k0 < K; k0 += BKK) {
        // ---- load A tile ----
        if (MODE == 1) {                 // A[K,M]: direct, rows of 128 floats
            #pragma unroll
            for (int i = 0; i < 2; i++) {
                int f = tid + i * 256;   // 0..511 float4 slots
                int kk = f >> 5, c4 = f & 31;
                float4 v = *(const float4*)(A + (size_t)(k0 + kk) * lda + bm + c4 * 4);
                if (rm) { float mv = rm[k0 + kk]; v.x *= mv; v.y *= mv; v.z *= mv; v.w *= mv; }
                *(float4*)&As[kk][c4 * 4] = v;
            }
        } else {                         // A[M,K]: transpose into smem
            #pragma unroll
            for (int i = 0; i < 2; i++) {
                int f = tid + i * 256;
                int r = f >> 2, c4 = f & 3;
                float4 v = *(const float4*)(A + (size_t)(bm + r) * lda + k0 + c4 * 4);
                As[c4 * 4 + 0][r] = v.x; As[c4 * 4 + 1][r] = v.y;
                As[c4 * 4 + 2][r] = v.z; As[c4 * 4 + 3][r] = v.w;
            }
        }
        // ---- load B tile ----
        if (MODE == 0) {                 // B[N,K]: transpose into smem
            #pragma unroll
            for (int i = 0; i < 2; i++) {
                int f = tid + i * 256;
                int r = f >> 2, c4 = f & 3;
                float4 v = *(const float4*)(B + (size_t)(bn + r) * ldb + k0 + c4 * 4);
                Bs[c4 * 4 + 0][r] = v.x; Bs[c4 * 4 + 1][r] = v.y;
                Bs[c4 * 4 + 2][r] = v.z; Bs[c4 * 4 + 3][r] = v.w;
            }
        } else {                         // B[K,N]: direct
            #pragma unroll
            for (int i = 0; i < 2; i++) {
                int f = tid + i * 256;
                int kk = f >> 5, c4 = f & 31;
                *(float4*)&Bs[kk][c4 * 4] =
                    *(const float4*)(B + (size_t)(k0 + kk) * ldb + bn + c4 * 4);
            }
        }
        __syncthreads();

        float t[8][8];
        #pragma unroll
        for (int i = 0; i < 8; i++)
            #pragma unroll
            for (int j = 0; j < 8; j++) t[i][j] = 0.f;

        #pragma unroll
        for (int kk = 0; kk < BKK; kk++) {
            float a[8], b[8];
            *(float4*)&a[0] = *(float4*)&As[kk][ty * 8];
            *(float4*)&a[4] = *(float4*)&As[kk][ty * 8 + 4];
            *(float4*)&b[0] = *(float4*)&Bs[kk][tx * 8];
            *(float4*)&b[4] = *(float4*)&Bs[kk][tx * 8 + 4];
            #pragma unroll
            for (int i = 0; i < 8; i++)
                #pragma unroll
                for (int j = 0; j < 8; j++)
                    t[i][j] += a[i] * b[j];
        }
        // fold slice partial into main accumulator (tree level)
        #pragma unroll
        for (int i = 0; i < 8; i++)
            #pragma unroll
            for (int j = 0; j < 8; j++) s[i][j] += t[i][j];
        __syncthreads();
    }
    // ---- epilogue ----
    #pragma unroll
    for (int i = 0; i < 8; i++) {
        int r = bm + ty * 8 + i;
        #pragma unroll
        for (int j = 0; j < 8; j += 4) {
            int c = bn + tx * 8 + j;
            float4 v = make_float4(s[i][j] * alpha, s[i][j+1] * alpha,
                                   s[i][j+2] * alpha, s[i][j+3] * alpha);
            if (bias) { v.x += bias[c]; v.y += bias[c+1]; v.z += bias[c+2]; v.w += bias[c+3]; }
            *(float4*)(C + (size_t)r * ldc + c) = v;
        }
    }
}

// ---------------- norms ----------------
__global__ void tile_norms_kernel() {
    int idx = blockIdx.x * 256 + threadIdx.x;     // 2*B*NTILE threads
    int which = idx / (B_ * NTILE);
    int rem   = idx % (B_ * NTILE);
    int b = rem / NTILE, t = rem % NTILE;
    int s2 = t / (E_ / 2), d2 = t % (E_ / 2);
    const float* p = g_qkv + (size_t)(b * S_ + 2 * s2) * QKV_LD + which * E_ + 2 * d2;
    float v00 = p[0], v01 = p[1], v10 = p[QKV_LD], v11 = p[QKV_LD + 1];
    float n = sqrtf(v00 * v00 + v01 * v01 + v10 * v10 + v11 * v11);
    (which ? g_norm_k : g_norm_q)[rem] = n;
}

__global__ void wo_norms_kernel(const float* __restrict__ WO) {
    __shared__ float sh[256];
    int row = blockIdx.x;                         // b*S + s
    const float* p = WO + (size_t)row * E_;
    float s = 0.f;
    for (int i = threadIdx.x; i < E_; i += 256) { float v = p[i]; s += v * v; }
    sh[threadIdx.x] = s; __syncthreads();
    for (int o = 128; o > 0; o >>= 1) {
        if (threadIdx.x < o) sh[threadIdx.x] += sh[threadIdx.x + o];
        __syncthreads();
    }
    if (threadIdx.x == 0) g_norm_wo[row] = sqrtf(sh[0]);
}

// ---------------- median via radix select on float bits ----------------
__global__ void sel_init_kernel() {
    int t = threadIdx.x;
    for (int s = 0; s < NSEL; s++) g_hist[s][t] = 0;
    if (t < NSEL) {
        g_prefix[t] = 0;
        g_kk[t] = (t < 8) ? (NTILE / 2) : (S_ / 2);   // 0-based index of upper-middle
        g_cntless[t] = 0;
        g_maxbelow[t] = 0;
    }
}

__global__ void sel_hist_kernel(int round) {
    __shared__ unsigned sh[256];
    int sel = blockIdx.y;
    const float* p; int n; sel_info(sel, &p, &n);
    sh[threadIdx.x] = 0; __syncthreads();
    unsigned himask = (round == 0) ? 0u : (0xFFFFFFFFu << (32 - 8 * round));
    unsigned pref = g_prefix[sel];
    int shift = 24 - 8 * round;
    for (int i = blockIdx.x * 256 + threadIdx.x; i < n; i += gridDim.x * 256) {
        unsigned bits = __float_as_uint(p[i]);
        if ((bits & himask) == pref) atomicAdd(&sh[(bits >> shift) & 255], 1u);
    }
    __syncthreads();
    if (sh[threadIdx.x]) atomicAdd(&g_hist[sel][threadIdx.x], sh[threadIdx.x]);
}

__global__ void sel_scan_kernel(int round) {
    int sel = threadIdx.x;
    if (sel >= NSEL) return;
    int need = g_kk[sel];
    unsigned cum = 0; int bin = 255;
    for (int i = 0; i < 256; i++) {
        unsigned c = g_hist[sel][i];
        if (cum + c > (unsigned)need) { bin = i; break; }
        cum += c;
    }
    g_kk[sel] = need - (int)cum;
    g_prefix[sel] |= ((unsigned)bin) << (24 - 8 * round);
    for (int i = 0; i < 256; i++) g_hist[sel][i] = 0;
}

__global__ void sel_fin1_kernel() {
    __shared__ unsigned scnt, smax;
    int sel = blockIdx.y;
    const float* p; int n; sel_info(sel, &p, &n);
    if (threadIdx.x == 0) { scnt = 0; smax = 0; }
    __syncthreads();
    float bval = __uint_as_float(g_prefix[sel]);
    unsigned cnt = 0, mx = 0;
    for (int i = blockIdx.x * 256 + threadIdx.x; i < n; i += gridDim.x * 256) {
        float v = p[i];
        if (v < bval) { cnt++; unsigned bv = __float_as_uint(v); if (bv > mx) mx = bv; }
    }
    atomicAdd(&scnt, cnt); atomicMax(&smax, mx);
    __syncthreads();
    if (threadIdx.x == 0) {
        if (scnt) atomicAdd(&g_cntless[sel], scnt);
        atomicMax(&g_maxbelow[sel], smax);
    }
}

__global__ void sel_fin2_kernel() {
    int sel = threadIdx.x;
    if (sel >= NSEL) return;
    unsigned kt = (sel < 8) ? (unsigned)(NTILE / 2) : (unsigned)(S_ / 2);
    float b = __uint_as_float(g_prefix[sel]);              // sorted[N/2]
    float a = (g_cntless[sel] == kt) ? __uint_as_float(g_maxbelow[sel]) : b; // sorted[N/2-1]
    g_thr[sel] = 0.5f * (a + b);                           // exact jnp.median
}

// ---------------- mask application ----------------
__global__ void mask_qk_kernel() {
    int idx = blockIdx.x * 256 + threadIdx.x;
    int which = idx / (B_ * NTILE);
    int rem   = idx % (B_ * NTILE);
    int b = rem / NTILE, t = rem % NTILE;
    float n = (which ? g_norm_k : g_norm_q)[rem];
    if (n < g_thr[which * 4 + b]) {
        int s2 = t / (E_ / 2), d2 = t % (E_ / 2);
        float* p = g_qkv + (size_t)(b * S_ + 2 * s2) * QKV_LD + which * E_ + 2 * d2;
        p[0] = 0.f; p[1] = 0.f; p[QKV_LD] = 0.f; p[QKV_LD + 1] = 0.f;
    }
}

__global__ void wmask_kernel() {
    int i = blockIdx.x * 256 + threadIdx.x;
    if (i >= B_ * S_) return;
    int b = i / S_;
    g_wmask[i] = (g_norm_wo[i] >= g_thr[8 + b]) ? 1.f : 0.f;
}

// ---------------- launch ----------------
extern "C" void kernel_launch(void* const* d_in, const int* in_sizes, int n_in,
                              void* d_out, int out_size)
{
    const float* x    = (const float*)d_in[0];   // [4,2048,1024]
    const float* Wqkv = (const float*)d_in[1];   // [3072,1024]
    const float* bqkv = (const float*)d_in[2];   // [3072]
    const float* WO   = (const float*)d_in[3];   // [4,1,2048,1024]
    float* out        = (float*)d_out;           // [4,2048,1024]
    (void)in_sizes; (void)n_in; (void)out_size;

    float *qkv, *Amat, *H1, *G, *T, *U, *wmask;
    cudaGetSymbolAddress((void**)&qkv,   g_qkv);
    cudaGetSymbolAddress((void**)&Amat,  g_Amat);
    cudaGetSymbolAddress((void**)&H1,    g_H1);
    cudaGetSymbolAddress((void**)&G,     g_G);
    cudaGetSymbolAddress((void**)&T,     g_T);
    cudaGetSymbolAddress((void**)&U,     g_U);
    cudaGetSymbolAddress((void**)&wmask, g_wmask);

    const size_t EE = (size_t)E_ * E_;
    const size_t SE = (size_t)S_ * E_;
    const size_t SQ = (size_t)S_ * QKV_LD;

    // 1) qkv = x @ Wqkv^T + bqkv    (NT, M=8192, N=3072, K=1024)
    sgemm_k<0><<<dim3(QKV_LD / BN, (B_ * S_) / BM, 1), 256>>>(
        x, E_, 0, Wqkv, E_, 0, qkv, QKV_LD, 0,
        B_ * S_, QKV_LD, E_, bqkv, nullptr, 0, 1.f);

    // 2) norms
    tile_norms_kernel<<<(2 * B_ * NTILE) / 256, 256>>>();
    wo_norms_kernel<<<B_ * S_, 256>>>(WO);

    // 3) medians (radix select, 4 rounds) + exact jax threshold
    sel_init_kernel<<<1, 256>>>();
    for (int r = 0; r < 4; r++) {
        sel_hist_kernel<<<dim3(64, NSEL), 256>>>(r);
        sel_scan_kernel<<<1, 32>>>(r);
    }
    sel_fin1_kernel<<<dim3(64, NSEL), 256>>>();
    sel_fin2_kernel<<<1, 32>>>();

    // 4) apply masks
    mask_qk_kernel<<<(2 * B_ * NTILE) / 256, 256>>>();
    wmask_kernel<<<(B_ * S_) / 256, 256>>>();

    // 5) E x E factors (TN, K=S), batched over B
    // A = Qp^T Kp
    sgemm_k<1><<<dim3(E_ / BN, E_ / BM, B_), 256>>>(
        qkv + 0, QKV_LD, SQ, qkv + E_, QKV_LD, SQ, Amat, E_, EE,
        E_, E_, S_, nullptr, nullptr, 0, 1.f);
    // H1 = x^T v
    sgemm_k<1><<<dim3(E_ / BN, E_ / BM, B_), 256>>>(
        x, E_, SE, qkv + 2 * E_, QKV_LD, SQ, H1, E_, EE,
        E_, E_, S_, nullptr, nullptr, 0, 1.f);
    // G = WO_^T x   (row mask on WO folded into load)
    sgemm_k<1><<<dim3(E_ / BN, E_ / BM, B_), 256>>>(
        WO, E_, SE, x, E_, SE, G, E_, EE,
        E_, E_, S_, nullptr, wmask, S_, 1.f);

    // 6) chain products (NN, 1024^3)
    sgemm_k<2><<<dim3(E_ / BN, E_ / BM, B_), 256>>>(
        H1, E_, EE, G, E_, EE, T, E_, EE,
        E_, E_, E_, nullptr, nullptr, 0, 1.f);
    sgemm_k<2><<<dim3(E_ / BN, E_ / BM, B_), 256>>>(
        Amat, E_, EE, T, E_, EE, U, E_, EE,
        E_, E_, E_, nullptr, nullptr, 0, 1.f / 32.f);

    // 7) out = x @ U   (NN, M=2048, N=1024, K=1024), batched
    sgemm_k<2><<<dim3(E_ / BN, S_ / BM, B_), 256>>>(
        x, E_, SE, U, E_, EE, out, E_, SE,
        S_, E_, E_, nullptr, nullptr, 0, 1.f);
}

// round 11
// speedup vs baseline: 1.4993x; 1.4993x over previous
#include <cuda_runtime.h>
#include <cuda_bf16.h>
#include <stdint.h>

#define B_    4
#define S_    2048
#define E_    1024
#define QKV_LD 3072
#define NTILE ((S_/2)*(E_/2))   // 524288 tiles per (b, q|k)
#define NSEL  12                // 0..3 q-batches, 4..7 k-batches, 8..11 WO-batches

// ======================= PTX helpers =======================
__device__ __forceinline__ uint32_t smem_u32(const void* p) {
    uint32_t a;
    asm("{ .reg .u64 t; cvta.to.shared.u64 t, %1; cvt.u32.u64 %0, t; }" : "=r"(a) : "l"(p));
    return a;
}
#define CP_ASYNC16(s, g) \
    asm volatile("cp.async.cg.shared.global [%0], [%1], 16;" :: "r"(s), "l"(g))
#define CP_COMMIT() asm volatile("cp.async.commit_group;" ::: "memory")
#define CP_WAIT1()  asm volatile("cp.async.wait_group 1;" ::: "memory")
#define CP_WAIT0()  asm volatile("cp.async.wait_group 0;" ::: "memory")
#define LDSM4(r0, r1, r2, r3, a) \
    asm volatile("ldmatrix.sync.aligned.m8n8.x4.shared.b16 {%0,%1,%2,%3}, [%4];" \
        : "=r"(r0), "=r"(r1), "=r"(r2), "=r"(r3) : "r"(a))
#define MMA16816(c, a, b) \
    asm volatile("mma.sync.aligned.m16n8k16.row.col.f32.bf16.bf16.f32 " \
        "{%0,%1,%2,%3}, {%4,%5,%6,%7}, {%8,%9}, {%0,%1,%2,%3};" \
        : "+f"((c)[0]), "+f"((c)[1]), "+f"((c)[2]), "+f"((c)[3]) \
        : "r"((a)[0]), "r"((a)[1]), "r"((a)[2]), "r"((a)[3]), "r"((b)[0]), "r"((b)[1]))

// 8x8-matrix-blocked smem layout for a 128x16 bf16 tile (4 KB)
__device__ __forceinline__ uint32_t tile_off(int row, int ks) {
    return (uint32_t)((((row >> 3) * 2 + ks) * 128) + ((((row & 7) ^ (ks * 2)) & 7) * 16));
}

// ======================= scratch (device globals) =======================
__device__ float g_qkv[B_*S_*QKV_LD];          // [b, s, 3E] fp32; first 16MB reused as scr later
__device__ float g_norm_q[B_*NTILE];
__device__ float g_norm_k[B_*NTILE];
__device__ float g_norm_wo[B_*S_];
__device__ float g_wmask[B_*S_];

// bf16 hi/lo splits (2-way downstream; value-noise only)
__device__ __nv_bfloat16 g_x0[B_*S_*E_],  g_x1[B_*S_*E_];
__device__ __nv_bfloat16 g_wv0[E_*E_],    g_wv1[E_*E_];    // v rows of Wqkv
__device__ __nv_bfloat16 g_xT0[B_*E_*S_], g_xT1[B_*E_*S_];
__device__ __nv_bfloat16 g_qT0[B_*E_*S_], g_qT1[B_*E_*S_];
__device__ __nv_bfloat16 g_kT0[B_*E_*S_], g_kT1[B_*E_*S_];
__device__ __nv_bfloat16 g_vT0[B_*E_*S_], g_vT1[B_*E_*S_];
__device__ __nv_bfloat16 g_oT0[B_*E_*S_], g_oT1[B_*E_*S_];
__device__ __nv_bfloat16 g_am0[B_*E_*E_], g_am1[B_*E_*E_];
__device__ __nv_bfloat16 g_h10[B_*E_*E_], g_h11[B_*E_*E_];
__device__ __nv_bfloat16 g_gt0[B_*E_*E_], g_gt1[B_*E_*E_];
__device__ __nv_bfloat16 g_tt0[B_*E_*E_], g_tt1[B_*E_*E_];
__device__ __nv_bfloat16 g_ut0[B_*E_*E_], g_ut1[B_*E_*E_];

__device__ unsigned g_hist[NSEL][256];
__device__ unsigned g_prefix[NSEL];
__device__ int      g_kk[NSEL];
__device__ unsigned g_cntless[NSEL];
__device__ unsigned g_maxbelow[NSEL];
__device__ float    g_thr[NSEL];

__device__ __forceinline__ void sel_info(int sel, const float** p, int* n) {
    if (sel < 4)      { *p = g_norm_q  + (size_t)sel * NTILE;       *n = NTILE; }
    else if (sel < 8) { *p = g_norm_k  + (size_t)(sel-4) * NTILE;   *n = NTILE; }
    else              { *p = g_norm_wo + (size_t)(sel-8) * S_;      *n = S_;    }
}

// ======================= fp32 SGEMM (EXACT R2 code, MODE 0 NT only) ==============
// C[M,N] = A[M,K] * B[N,K]^T (+bias). Bit-identical to the R2 passing kernel
// for the q,k columns -> bit-identical norms/masks.
#define BM 128
#define BN 128
#define BKK 16

__global__ void __launch_bounds__(256, 1) sgemm_nt(
    const float* __restrict__ A, int lda,
    const float* __restrict__ B, int ldb,
    float* __restrict__ C, int ldc,
    int M, int N, int K,
    const float* __restrict__ bias)
{
    __shared__ float As[BKK][BM];
    __shared__ float Bs[BKK][BN];
    const int bm = blockIdx.y * BM, bn = blockIdx.x * BN;
    const int tid = threadIdx.x;
    const int tx = tid & 15, ty = tid >> 4;

    float s[8][8];
    #pragma unroll
    for (int i = 0; i < 8; i++)
        #pragma unroll
        for (int j = 0; j < 8; j++) s[i][j] = 0.f;

    for (int k0 = 0; k0 < K; k0 += BKK) {
        #pragma unroll
        for (int i = 0; i < 2; i++) {
            int f = tid + i * 256;
            int r = f >> 2, c4 = f & 3;
            float4 v = *(const float4*)(A + (size_t)(bm + r) * lda + k0 + c4 * 4);
            As[c4 * 4 + 0][r] = v.x; As[c4 * 4 + 1][r] = v.y;
            As[c4 * 4 + 2][r] = v.z; As[c4 * 4 + 3][r] = v.w;
        }
        #pragma unroll
        for (int i = 0; i < 2; i++) {
            int f = tid + i * 256;
            int r = f >> 2, c4 = f & 3;
            float4 v = *(const float4*)(B + (size_t)(bn + r) * ldb + k0 + c4 * 4);
            Bs[c4 * 4 + 0][r] = v.x; Bs[c4 * 4 + 1][r] = v.y;
            Bs[c4 * 4 + 2][r] = v.z; Bs[c4 * 4 + 3][r] = v.w;
        }
        __syncthreads();

        float t[8][8];
        #pragma unroll
        for (int i = 0; i < 8; i++)
            #pragma unroll
            for (int j = 0; j < 8; j++) t[i][j] = 0.f;

        #pragma unroll
        for (int kk = 0; kk < BKK; kk++) {
            float a[8], b[8];
            *(float4*)&a[0] = *(float4*)&As[kk][ty * 8];
            *(float4*)&a[4] = *(float4*)&As[kk][ty * 8 + 4];
            *(float4*)&b[0] = *(float4*)&Bs[kk][tx * 8];
            *(float4*)&b[4] = *(float4*)&Bs[kk][tx * 8 + 4];
            #pragma unroll
            for (int i = 0; i < 8; i++)
                #pragma unroll
                for (int j = 0; j < 8; j++)
                    t[i][j] += a[i] * b[j];
        }
        #pragma unroll
        for (int i = 0; i < 8; i++)
            #pragma unroll
            for (int j = 0; j < 8; j++) s[i][j] += t[i][j];
        __syncthreads();
    }
    #pragma unroll
    for (int i = 0; i < 8; i++) {
        int r = bm + ty * 8 + i;
        #pragma unroll
        for (int j = 0; j < 8; j += 4) {
            int c = bn + tx * 8 + j;
            float4 v = make_float4(s[i][j] * 1.f, s[i][j+1] * 1.f,
                                   s[i][j+2] * 1.f, s[i][j+3] * 1.f);
            if (bias) { v.x += bias[c]; v.y += bias[c+1]; v.z += bias[c+2]; v.w += bias[c+3]; }
            *(float4*)(C + (size_t)r * ldc + c) = v;
        }
    }
}

// ======================= warp-MMA NT GEMM (bf16x3, fp32 accum) =======================
// C[i,j] = alpha * sum_k (A0B0 + A0B1 + A1B0) (+bias[j]); ldc row stride.
__global__ void __launch_bounds__(256, 1) mma_nt(
    const __nv_bfloat16* __restrict__ A0, const __nv_bfloat16* __restrict__ A1, size_t sA,
    const __nv_bfloat16* __restrict__ B0, const __nv_bfloat16* __restrict__ B1, size_t sB,
    float* __restrict__ C, size_t sC, int ldc,
    int M, int N, int K,
    const float* __restrict__ bias, float alpha)
{
    __shared__ __align__(128) char smem[2 * 16384];
    const uint32_t sbase = smem_u32(smem);
    const int tid = threadIdx.x;
    const int wid = tid >> 5, lane = tid & 31;
    const int bz = blockIdx.z;
    const __nv_bfloat16* Apl0 = A0 + (size_t)bz * sA;
    const __nv_bfloat16* Apl1 = A1 + (size_t)bz * sA;
    const __nv_bfloat16* Bpl0 = B0 + (size_t)bz * sB;
    const __nv_bfloat16* Bpl1 = B1 + (size_t)bz * sB;
    C += (size_t)bz * sC;
    const int bm = blockIdx.y * 128, bn = blockIdx.x * 128;
    const int nch = K >> 4;

    const int lr0 = tid >> 1, lks0 = tid & 1;
    const uint32_t so0 = tile_off(lr0, lks0);

    const int j01 = (lane >> 3) & 1;
    const int j23 = lane >> 4;
    const int lr  = lane & 7;
    const int wm = (wid & 3) * 32;
    const int wn = (wid >> 2) * 64;
    uint32_t aoff[2], boff[4];
    #pragma unroll
    for (int mf = 0; mf < 2; ++mf)
        aoff[mf] = tile_off(wm + mf * 16 + j01 * 8 + lr, j23);
    #pragma unroll
    for (int nf2 = 0; nf2 < 4; ++nf2)
        boff[nf2] = tile_off(wn + nf2 * 16 + j23 * 8 + lr, j01);

    float acc[2][8][4];
    #pragma unroll
    for (int mf = 0; mf < 2; ++mf)
        #pragma unroll
        for (int nf = 0; nf < 8; ++nf)
            #pragma unroll
            for (int q = 0; q < 4; ++q) acc[mf][nf][q] = 0.f;

    #pragma unroll 1
    for (int pc = 0; pc < 2 && pc < nch; ++pc) {
        uint32_t base = sbase + (uint32_t)pc * 16384u;
        int k0 = pc << 4;
        size_t gA = (size_t)(bm + lr0) * K + k0 + lks0 * 8;
        size_t gB = (size_t)(bn + lr0) * K + k0 + lks0 * 8;
        CP_ASYNC16(base + so0,         Apl0 + gA);
        CP_ASYNC16(base + 4096 + so0,  Apl1 + gA);
        CP_ASYNC16(base + 8192 + so0,  Bpl0 + gB);
        CP_ASYNC16(base + 12288 + so0, Bpl1 + gB);
        CP_COMMIT();
    }

    for (int c = 0; c < nch; ++c) {
        if (c + 1 < nch) { CP_WAIT1(); } else { CP_WAIT0(); }
        __syncthreads();
        const uint32_t base = sbase + (uint32_t)(c & 1) * 16384u;
        uint32_t af[2][2][4];
        #pragma unroll
        for (int mf = 0; mf < 2; ++mf) {
            LDSM4(af[0][mf][0], af[0][mf][1], af[0][mf][2], af[0][mf][3],
                  base + aoff[mf]);
            LDSM4(af[1][mf][0], af[1][mf][1], af[1][mf][2], af[1][mf][3],
                  base + 4096 + aoff[mf]);
        }
        uint32_t bf[2][8][2];
        #pragma unroll
        for (int s = 0; s < 2; ++s)
            #pragma unroll
            for (int nf2 = 0; nf2 < 4; ++nf2) {
                uint32_t r0, r1, r2, r3;
                LDSM4(r0, r1, r2, r3, base + 8192 + s * 4096 + boff[nf2]);
                bf[s][nf2*2][0] = r0;   bf[s][nf2*2][1] = r1;
                bf[s][nf2*2+1][0] = r2; bf[s][nf2*2+1][1] = r3;
            }
        #pragma unroll
        for (int mf = 0; mf < 2; ++mf)
            #pragma unroll
            for (int nf = 0; nf < 8; ++nf) {
                MMA16816(acc[mf][nf], af[0][mf], bf[0][nf]);
                MMA16816(acc[mf][nf], af[0][mf], bf[1][nf]);
                MMA16816(acc[mf][nf], af[1][mf], bf[0][nf]);
            }
        __syncthreads();
        if (c + 2 < nch) {
            uint32_t b2 = sbase + (uint32_t)(c & 1) * 16384u;
            int k0 = (c + 2) << 4;
            size_t gA = (size_t)(bm + lr0) * K + k0 + lks0 * 8;
            size_t gB = (size_t)(bn + lr0) * K + k0 + lks0 * 8;
            CP_ASYNC16(b2 + so0,         Apl0 + gA);
            CP_ASYNC16(b2 + 4096 + so0,  Apl1 + gA);
            CP_ASYNC16(b2 + 8192 + so0,  Bpl0 + gB);
            CP_ASYNC16(b2 + 12288 + so0, Bpl1 + gB);
            CP_COMMIT();
        }
    }

    const int er = lane >> 2, ec = (lane & 3) * 2;
    #pragma unroll
    for (int mf = 0; mf < 2; ++mf)
        #pragma unroll
        for (int nf = 0; nf < 8; ++nf) {
            int row = bm + wm + mf * 16 + er;
            int col = bn + wn + nf * 8 + ec;
            float bx = 0.f, by = 0.f;
            if (bias) { bx = bias[col]; by = bias[col + 1]; }
            float2 v0 = { acc[mf][nf][0] * alpha + bx, acc[mf][nf][1] * alpha + by };
            float2 v1 = { acc[mf][nf][2] * alpha + bx, acc[mf][nf][3] * alpha + by };
            *(float2*)(C + (size_t)row * ldc + col) = v0;
            *(float2*)(C + (size_t)(row + 8) * ldc + col) = v1;
        }
}

// ======================= split / transpose-split (2-way) =======================
__global__ void split_kernel(const float* __restrict__ src,
                             __nv_bfloat16* __restrict__ d0,
                             __nv_bfloat16* __restrict__ d1, size_t n4)
{
    for (size_t i = (size_t)blockIdx.x * 256 + threadIdx.x; i < n4;
         i += (size_t)gridDim.x * 256) {
        float4 v = ((const float4*)src)[i];
        float vv[4] = { v.x, v.y, v.z, v.w };
        __nv_bfloat16 h0[4], h1[4];
        #pragma unroll
        for (int t = 0; t < 4; t++) {
            h0[t] = __float2bfloat16(vv[t]);
            h1[t] = __float2bfloat16(vv[t] - __bfloat162float(h0[t]));
        }
        ((__nv_bfloat162*)d0)[2*i]   = __nv_bfloat162(h0[0], h0[1]);
        ((__nv_bfloat162*)d0)[2*i+1] = __nv_bfloat162(h0[2], h0[3]);
        ((__nv_bfloat162*)d1)[2*i]   = __nv_bfloat162(h1[0], h1[1]);
        ((__nv_bfloat162*)d1)[2*i+1] = __nv_bfloat162(h1[2], h1[3]);
    }
}

__global__ void tsplit_kernel(const float* __restrict__ src, int ld, size_t sSrc,
                              const float* __restrict__ mask,
                              __nv_bfloat16* __restrict__ d0,
                              __nv_bfloat16* __restrict__ d1)
{
    __shared__ float tile[32][33];
    int bz = blockIdx.z;
    src += (size_t)bz * sSrc;
    const float* mk = mask ? (mask + (size_t)bz * S_) : nullptr;
    __nv_bfloat16* p0 = d0 + (size_t)bz * E_ * S_;
    __nv_bfloat16* p1 = d1 + (size_t)bz * E_ * S_;
    int e0 = blockIdx.x * 32, s0 = blockIdx.y * 32;
    int tx = threadIdx.x & 31, ty = threadIdx.x >> 5;
    #pragma unroll
    for (int i = ty; i < 32; i += 8) {
        float v = src[(size_t)(s0 + i) * ld + e0 + tx];
        if (mk) v *= mk[s0 + i];
        tile[i][tx] = v;
    }
    __syncthreads();
    #pragma unroll
    for (int i = ty; i < 32; i += 8) {
        float v = tile[tx][i];
        __nv_bfloat16 h = __float2bfloat16(v);
        __nv_bfloat16 l = __float2bfloat16(v - __bfloat162float(h));
        p0[(size_t)(e0 + i) * S_ + s0 + tx] = h;
        p1[(size_t)(e0 + i) * S_ + s0 + tx] = l;
    }
}

// ======================= norms =======================
__global__ void tile_norms_kernel() {
    int idx = blockIdx.x * 256 + threadIdx.x;
    int which = idx / (B_ * NTILE);
    int rem   = idx % (B_ * NTILE);
    int b = rem / NTILE, t = rem % NTILE;
    int s2 = t / (E_ / 2), d2 = t % (E_ / 2);
    const float* p = g_qkv + (size_t)(b * S_ + 2 * s2) * QKV_LD + which * E_ + 2 * d2;
    float v00 = p[0], v01 = p[1], v10 = p[QKV_LD], v11 = p[QKV_LD + 1];
    float n = sqrtf(v00 * v00 + v01 * v01 + v10 * v10 + v11 * v11);
    (which ? g_norm_k : g_norm_q)[rem] = n;
}

__global__ void wo_norms_kernel(const float* __restrict__ WO) {
    __shared__ float sh[256];
    int row = blockIdx.x;
    const float* p = WO + (size_t)row * E_;
    float s = 0.f;
    for (int i = threadIdx.x; i < E_; i += 256) { float v = p[i]; s += v * v; }
    sh[threadIdx.x] = s; __syncthreads();
    for (int o = 128; o > 0; o >>= 1) {
        if (threadIdx.x < o) sh[threadIdx.x] += sh[threadIdx.x + o];
        __syncthreads();
    }
    if (threadIdx.x == 0) g_norm_wo[row] = sqrtf(sh[0]);
}

// ======================= median via radix select =======================
__global__ void sel_init_kernel() {
    int t = threadIdx.x;
    for (int s = 0; s < NSEL; s++) g_hist[s][t] = 0;
    if (t < NSEL) {
        g_prefix[t] = 0;
        g_kk[t] = (t < 8) ? (NTILE / 2) : (S_ / 2);
        g_cntless[t] = 0;
        g_maxbelow[t] = 0;
    }
}

__global__ void sel_hist_kernel(int round) {
    __shared__ unsigned sh[256];
    int sel = blockIdx.y;
    const float* p; int n; sel_info(sel, &p, &n);
    sh[threadIdx.x] = 0; __syncthreads();
    unsigned himask = (round == 0) ? 0u : (0xFFFFFFFFu << (32 - 8 * round));
    unsigned pref = g_prefix[sel];
    int shift = 24 - 8 * round;
    for (int i = blockIdx.x * 256 + threadIdx.x; i < n; i += gridDim.x * 256) {
        unsigned bits = __float_as_uint(p[i]);
        if ((bits & himask) == pref) atomicAdd(&sh[(bits >> shift) & 255], 1u);
    }
    __syncthreads();
    if (sh[threadIdx.x]) atomicAdd(&g_hist[sel][threadIdx.x], sh[threadIdx.x]);
}

__global__ void sel_scan_kernel(int round) {
    int sel = threadIdx.x;
    if (sel >= NSEL) return;
    int need = g_kk[sel];
    unsigned cum = 0; int bin = 255;
    for (int i = 0; i < 256; i++) {
        unsigned c = g_hist[sel][i];
        if (cum + c > (unsigned)need) { bin = i; break; }
        cum += c;
    }
    g_kk[sel] = need - (int)cum;
    g_prefix[sel] |= ((unsigned)bin) << (24 - 8 * round);
    for (int i = 0; i < 256; i++) g_hist[sel][i] = 0;
}

__global__ void sel_fin1_kernel() {
    __shared__ unsigned scnt, smax;
    int sel = blockIdx.y;
    const float* p; int n; sel_info(sel, &p, &n);
    if (threadIdx.x == 0) { scnt = 0; smax = 0; }
    __syncthreads();
    float bval = __uint_as_float(g_prefix[sel]);
    unsigned cnt = 0, mx = 0;
    for (int i = blockIdx.x * 256 + threadIdx.x; i < n; i += gridDim.x * 256) {
        float v = p[i];
        if (v < bval) { cnt++; unsigned bv = __float_as_uint(v); if (bv > mx) mx = bv; }
    }
    atomicAdd(&scnt, cnt); atomicMax(&smax, mx);
    __syncthreads();
    if (threadIdx.x == 0) {
        if (scnt) atomicAdd(&g_cntless[sel], scnt);
        atomicMax(&g_maxbelow[sel], smax);
    }
}

__global__ void sel_fin2_kernel() {
    int sel = threadIdx.x;
    if (sel >= NSEL) return;
    unsigned kt = (sel < 8) ? (unsigned)(NTILE / 2) : (unsigned)(S_ / 2);
    float b = __uint_as_float(g_prefix[sel]);
    float a = (g_cntless[sel] == kt) ? __uint_as_float(g_maxbelow[sel]) : b;
    g_thr[sel] = 0.5f * (a + b);
}

// ======================= mask application =======================
__global__ void mask_qk_kernel() {
    int idx = blockIdx.x * 256 + threadIdx.x;
    int which = idx / (B_ * NTILE);
    int rem   = idx % (B_ * NTILE);
    int b = rem / NTILE, t = rem % NTILE;
    float n = (which ? g_norm_k : g_norm_q)[rem];
    if (n < g_thr[which * 4 + b]) {
        int s2 = t / (E_ / 2), d2 = t % (E_ / 2);
        float* p = g_qkv + (size_t)(b * S_ + 2 * s2) * QKV_LD + which * E_ + 2 * d2;
        p[0] = 0.f; p[1] = 0.f; p[QKV_LD] = 0.f; p[QKV_LD + 1] = 0.f;
    }
}

__global__ void wmask_kernel() {
    int i = blockIdx.x * 256 + threadIdx.x;
    if (i >= B_ * S_) return;
    int b = i / S_;
    g_wmask[i] = (g_norm_wo[i] >= g_thr[8 + b]) ? 1.f : 0.f;
}

// ======================= launch =======================
extern "C" void kernel_launch(void* const* d_in, const int* in_sizes, int n_in,
                              void* d_out, int out_size)
{
    const float* x    = (const float*)d_in[0];   // [4,2048,1024]
    const float* Wqkv = (const float*)d_in[1];   // [3072,1024]
    const float* bqkv = (const float*)d_in[2];   // [3072]
    const float* WO   = (const float*)d_in[3];   // [4,1,2048,1024]
    float* out        = (float*)d_out;           // [4,2048,1024]
    (void)in_sizes; (void)n_in; (void)out_size;

    float *qkv, *wmask;
    cudaGetSymbolAddress((void**)&qkv,   g_qkv);
    cudaGetSymbolAddress((void**)&wmask, g_wmask);
    float* scr = qkv;   // fp32 E x E scratch (16 MB), reused after qkv fp32 is dead
    __nv_bfloat16 *x0,*x1, *wv0,*wv1, *xT0,*xT1, *qT0,*qT1, *kT0,*kT1,
                  *vT0,*vT1, *oT0,*oT1, *am0,*am1, *h10,*h11, *gt0,*gt1,
                  *tt0,*tt1, *ut0,*ut1;
    cudaGetSymbolAddress((void**)&x0, g_x0); cudaGetSymbolAddress((void**)&x1, g_x1);
    cudaGetSymbolAddress((void**)&wv0, g_wv0); cudaGetSymbolAddress((void**)&wv1, g_wv1);
    cudaGetSymbolAddress((void**)&xT0, g_xT0); cudaGetSymbolAddress((void**)&xT1, g_xT1);
    cudaGetSymbolAddress((void**)&qT0, g_qT0); cudaGetSymbolAddress((void**)&qT1, g_qT1);
    cudaGetSymbolAddress((void**)&kT0, g_kT0); cudaGetSymbolAddress((void**)&kT1, g_kT1);
    cudaGetSymbolAddress((void**)&vT0, g_vT0); cudaGetSymbolAddress((void**)&vT1, g_vT1);
    cudaGetSymbolAddress((void**)&oT0, g_oT0); cudaGetSymbolAddress((void**)&oT1, g_oT1);
    cudaGetSymbolAddress((void**)&am0, g_am0); cudaGetSymbolAddress((void**)&am1, g_am1);
    cudaGetSymbolAddress((void**)&h10, g_h10); cudaGetSymbolAddress((void**)&h11, g_h11);
    cudaGetSymbolAddress((void**)&gt0, g_gt0); cudaGetSymbolAddress((void**)&gt1, g_gt1);
    cudaGetSymbolAddress((void**)&tt0, g_tt0); cudaGetSymbolAddress((void**)&tt1, g_tt1);
    cudaGetSymbolAddress((void**)&ut0, g_ut0); cudaGetSymbolAddress((void**)&ut1, g_ut1);

    const size_t EE = (size_t)E_ * E_;
    const size_t SE = (size_t)S_ * E_;
    const size_t ES = (size_t)E_ * S_;

    // 1) 2-way splits of x and the v-rows of Wqkv
    split_kernel<<<2048, 256>>>(x, x0, x1, B_*SE/4);
    split_kernel<<<2048, 256>>>(Wqkv + 2048 * E_, wv0, wv1, EE/4);

    // 2a) q,k columns: EXACT fp32 SGEMM (bit-identical to R2 -> bit-identical masks)
    sgemm_nt<<<dim3(2048 / BN, (B_ * S_) / BM, 1), 256>>>(
        x, E_, Wqkv, E_, qkv, QKV_LD, B_ * S_, 2048, E_, bqkv);
    // 2b) v columns: bf16x3 warp-MMA (value-noise only; never feeds norms)
    mma_nt<<<dim3(E_/128, (B_*S_)/128, 1), 256>>>(
        x0, x1, 0, wv0, wv1, 0, qkv + 2048, 0, QKV_LD,
        B_*S_, E_, E_, bqkv + 2048, 1.f);

    // 3) norms + medians + masks (bit-accurate path, identical to R2)
    tile_norms_kernel<<<(2 * B_ * NTILE) / 256, 256>>>();
    wo_norms_kernel<<<B_ * S_, 256>>>(WO);
    sel_init_kernel<<<1, 256>>>();
    for (int r = 0; r < 4; r++) {
        sel_hist_kernel<<<dim3(64, NSEL), 256>>>(r);
        sel_scan_kernel<<<1, 32>>>(r);
    }
    sel_fin1_kernel<<<dim3(64, NSEL), 256>>>();
    sel_fin2_kernel<<<1, 32>>>();
    mask_qk_kernel<<<(2 * B_ * NTILE) / 256, 256>>>();
    wmask_kernel<<<(B_ * S_) / 256, 256>>>();

    // 4) transpose + 2-way split operands for the TN factors
    dim3 tg(E_/32, S_/32, B_);
    tsplit_kernel<<<tg, 256>>>(x, E_, SE, nullptr, xT0, xT1);
    tsplit_kernel<<<tg, 256>>>(qkv + 0,     QKV_LD, (size_t)S_*QKV_LD, nullptr, qT0, qT1);
    tsplit_kernel<<<tg, 256>>>(qkv + E_,    QKV_LD, (size_t)S_*QKV_LD, nullptr, kT0, kT1);
    tsplit_kernel<<<tg, 256>>>(qkv + 2*E_,  QKV_LD, (size_t)S_*QKV_LD, nullptr, vT0, vT1);
    tsplit_kernel<<<tg, 256>>>(WO, E_, SE, wmask, oT0, oT1);
    // qkv fp32 is dead from here on; scr (= qkv) becomes the fp32 E x E scratch.

    // 5) E x E factors (bf16x3, K = S); each GEMM -> scr -> immediate bf16 split
    dim3 ge(E_/128, E_/128, B_);
    mma_nt<<<ge, 256>>>(qT0, qT1, ES, kT0, kT1, ES,
                        scr, EE, E_, E_, E_, S_, nullptr, 1.f);           // A = Qp^T Kp
    split_kernel<<<2048, 256>>>(scr, am0, am1, B_*EE/4);
    mma_nt<<<ge, 256>>>(xT0, xT1, ES, vT0, vT1, ES,
                        scr, EE, E_, E_, E_, S_, nullptr, 1.f);           // H1 = x^T v
    split_kernel<<<2048, 256>>>(scr, h10, h11, B_*EE/4);
    mma_nt<<<ge, 256>>>(xT0, xT1, ES, oT0, oT1, ES,
                        scr, EE, E_, E_, E_, S_, nullptr, 1.f);           // Gt = (WO_^T x)^T
    split_kernel<<<2048, 256>>>(scr, gt0, gt1, B_*EE/4);

    // 6) chain: Tt = Gt * H1^T (NT), Ut = Tt * A^T (NT) / 32
    mma_nt<<<ge, 256>>>(gt0, gt1, EE, h10, h11, EE,
                        scr, EE, E_, E_, E_, E_, nullptr, 1.f);           // Tt
    split_kernel<<<2048, 256>>>(scr, tt0, tt1, B_*EE/4);
    mma_nt<<<ge, 256>>>(tt0, tt1, EE, am0, am1, EE,
                        scr, EE, E_, E_, E_, E_, nullptr, 1.f / 32.f);    // Ut
    split_kernel<<<2048, 256>>>(scr, ut0, ut1, B_*EE/4);

    // 7) out = x @ U  (NT vs Ut, bf16x3)
    mma_nt<<<dim3(E_/128, S_/128, B_), 256>>>(
        x0, x1, SE, ut0, ut1, EE,
        out, SE, E_, S_, E_, E_, nullptr, 1.f);
}

// round 12
// speedup vs baseline: 1.6949x; 1.1305x over previous
#include <cuda_runtime.h>
#include <cuda_bf16.h>
#include <stdint.h>

#define B_    4
#define S_    2048
#define E_    1024
#define QKV_LD 3072
#define NTILE ((S_/2)*(E_/2))   // 524288 tiles per (b, q|k)
#define NSEL  12                // 0..3 q-batches, 4..7 k-batches, 8..11 WO-batches

// ======================= PTX helpers =======================
__device__ __forceinline__ uint32_t smem_u32(const void* p) {
    uint32_t a;
    asm("{ .reg .u64 t; cvta.to.shared.u64 t, %1; cvt.u32.u64 %0, t; }" : "=r"(a) : "l"(p));
    return a;
}
#define CP_ASYNC16(s, g) \
    asm volatile("cp.async.cg.shared.global [%0], [%1], 16;" :: "r"(s), "l"(g))
#define CP_COMMIT() asm volatile("cp.async.commit_group;" ::: "memory")
#define CP_WAIT1()  asm volatile("cp.async.wait_group 1;" ::: "memory")
#define CP_WAIT0()  asm volatile("cp.async.wait_group 0;" ::: "memory")
#define LDSM4(r0, r1, r2, r3, a) \
    asm volatile("ldmatrix.sync.aligned.m8n8.x4.shared.b16 {%0,%1,%2,%3}, [%4];" \
        : "=r"(r0), "=r"(r1), "=r"(r2), "=r"(r3) : "r"(a))
#define MMA16816(c, a, b) \
    asm volatile("mma.sync.aligned.m16n8k16.row.col.f32.bf16.bf16.f32 " \
        "{%0,%1,%2,%3}, {%4,%5,%6,%7}, {%8,%9}, {%0,%1,%2,%3};" \
        : "+f"((c)[0]), "+f"((c)[1]), "+f"((c)[2]), "+f"((c)[3]) \
        : "r"((a)[0]), "r"((a)[1]), "r"((a)[2]), "r"((a)[3]), "r"((b)[0]), "r"((b)[1]))

// 8x8-matrix-blocked smem layout for a 128x16 bf16 tile (4 KB)
__device__ __forceinline__ uint32_t tile_off(int row, int ks) {
    return (uint32_t)((((row >> 3) * 2 + ks) * 128) + ((((row & 7) ^ (ks * 2)) & 7) * 16));
}

// ======================= scratch (device globals) =======================
__device__ float g_qkv[B_*S_*QKV_LD];          // [b, s, 3E] fp32
__device__ float g_norm_q[B_*NTILE];
__device__ float g_norm_k[B_*NTILE];
__device__ float g_norm_wo[B_*S_];
__device__ float g_wmask[B_*S_];

// bf16 hi/lo splits (2-way downstream; value-noise only)
__device__ __nv_bfloat16 g_x0[B_*S_*E_],  g_x1[B_*S_*E_];
__device__ __nv_bfloat16 g_wv0[E_*E_],    g_wv1[E_*E_];    // v rows of Wqkv
__device__ __nv_bfloat16 g_xT0[B_*E_*S_], g_xT1[B_*E_*S_];
__device__ __nv_bfloat16 g_qT0[B_*E_*S_], g_qT1[B_*E_*S_];
__device__ __nv_bfloat16 g_kT0[B_*E_*S_], g_kT1[B_*E_*S_];
__device__ __nv_bfloat16 g_vT0[B_*E_*S_], g_vT1[B_*E_*S_];
__device__ __nv_bfloat16 g_oT0[B_*E_*S_], g_oT1[B_*E_*S_];
__device__ __nv_bfloat16 g_am0[B_*E_*E_], g_am1[B_*E_*E_];
__device__ __nv_bfloat16 g_h10[B_*E_*E_], g_h11[B_*E_*E_];
__device__ __nv_bfloat16 g_gt0[B_*E_*E_], g_gt1[B_*E_*E_];
__device__ __nv_bfloat16 g_tt0[B_*E_*E_], g_tt1[B_*E_*E_];
__device__ __nv_bfloat16 g_ut0[B_*E_*E_], g_ut1[B_*E_*E_];

__device__ unsigned g_hist[NSEL][256];
__device__ unsigned g_prefix[NSEL];
__device__ int      g_kk[NSEL];
__device__ unsigned g_cntless[NSEL];
__device__ unsigned g_maxbelow[NSEL];
__device__ float    g_thr[NSEL];

__device__ __forceinline__ void sel_info(int sel, const float** p, int* n) {
    if (sel < 4)      { *p = g_norm_q  + (size_t)sel * NTILE;       *n = NTILE; }
    else if (sel < 8) { *p = g_norm_k  + (size_t)(sel-4) * NTILE;   *n = NTILE; }
    else              { *p = g_norm_wo + (size_t)(sel-8) * S_;      *n = S_;    }
}

// ======================= fp32 SGEMM (EXACT R2 code, NT) ==============
// Bit-identical to the R2/R11 passing kernels for q,k -> bit-identical masks.
#define BM 128
#define BN 128
#define BKK 16

__global__ void __launch_bounds__(256, 1) sgemm_nt(
    const float* __restrict__ A, int lda,
    const float* __restrict__ B, int ldb,
    float* __restrict__ C, int ldc,
    int M, int N, int K,
    const float* __restrict__ bias)
{
    __shared__ float As[BKK][BM];
    __shared__ float Bs[BKK][BN];
    const int bm = blockIdx.y * BM, bn = blockIdx.x * BN;
    const int tid = threadIdx.x;
    const int tx = tid & 15, ty = tid >> 4;

    float s[8][8];
    #pragma unroll
    for (int i = 0; i < 8; i++)
        #pragma unroll
        for (int j = 0; j < 8; j++) s[i][j] = 0.f;

    for (int k0 = 0; k0 < K; k0 += BKK) {
        #pragma unroll
        for (int i = 0; i < 2; i++) {
            int f = tid + i * 256;
            int r = f >> 2, c4 = f & 3;
            float4 v = *(const float4*)(A + (size_t)(bm + r) * lda + k0 + c4 * 4);
            As[c4 * 4 + 0][r] = v.x; As[c4 * 4 + 1][r] = v.y;
            As[c4 * 4 + 2][r] = v.z; As[c4 * 4 + 3][r] = v.w;
        }
        #pragma unroll
        for (int i = 0; i < 2; i++) {
            int f = tid + i * 256;
            int r = f >> 2, c4 = f & 3;
            float4 v = *(const float4*)(B + (size_t)(bn + r) * ldb + k0 + c4 * 4);
            Bs[c4 * 4 + 0][r] = v.x; Bs[c4 * 4 + 1][r] = v.y;
            Bs[c4 * 4 + 2][r] = v.z; Bs[c4 * 4 + 3][r] = v.w;
        }
        __syncthreads();

        float t[8][8];
        #pragma unroll
        for (int i = 0; i < 8; i++)
            #pragma unroll
            for (int j = 0; j < 8; j++) t[i][j] = 0.f;

        #pragma unroll
        for (int kk = 0; kk < BKK; kk++) {
            float a[8], b[8];
            *(float4*)&a[0] = *(float4*)&As[kk][ty * 8];
            *(float4*)&a[4] = *(float4*)&As[kk][ty * 8 + 4];
            *(float4*)&b[0] = *(float4*)&Bs[kk][tx * 8];
            *(float4*)&b[4] = *(float4*)&Bs[kk][tx * 8 + 4];
            #pragma unroll
            for (int i = 0; i < 8; i++)
                #pragma unroll
                for (int j = 0; j < 8; j++)
                    t[i][j] += a[i] * b[j];
        }
        #pragma unroll
        for (int i = 0; i < 8; i++)
            #pragma unroll
            for (int j = 0; j < 8; j++) s[i][j] += t[i][j];
        __syncthreads();
    }
    #pragma unroll
    for (int i = 0; i < 8; i++) {
        int r = bm + ty * 8 + i;
        #pragma unroll
        for (int j = 0; j < 8; j += 4) {
            int c = bn + tx * 8 + j;
            float4 v = make_float4(s[i][j] * 1.f, s[i][j+1] * 1.f,
                                   s[i][j+2] * 1.f, s[i][j+3] * 1.f);
            if (bias) { v.x += bias[c]; v.y += bias[c+1]; v.z += bias[c+2]; v.w += bias[c+3]; }
            *(float4*)(C + (size_t)r * ldc + c) = v;
        }
    }
}

// ======================= warp-MMA NT GEMM (bf16x3, fp32 accum) =======================
// C[i,j] = alpha * sum_k (A0B0 + A1B0 + A0B1) (+bias[j]).
// Output: fp32 C (D0==null) OR fused hi/lo bf16 split to D0/D1.
// 128x128 CTA tile, BK=16, 2-stage cp.async. Restructured for <=128 regs (2 CTAs/SM).
__global__ void __launch_bounds__(256, 2) mma_nt(
    const __nv_bfloat16* __restrict__ A0, const __nv_bfloat16* __restrict__ A1, size_t sA,
    const __nv_bfloat16* __restrict__ B0, const __nv_bfloat16* __restrict__ B1, size_t sB,
    float* __restrict__ C,
    __nv_bfloat16* __restrict__ D0, __nv_bfloat16* __restrict__ D1,
    size_t sC, int ldc,
    int M, int N, int K,
    const float* __restrict__ bias, float alpha)
{
    __shared__ __align__(128) char smem[2 * 16384];
    const uint32_t sbase = smem_u32(smem);
    const int tid = threadIdx.x;
    const int wid = tid >> 5, lane = tid & 31;
    const int bz = blockIdx.z;
    const __nv_bfloat16* Apl0 = A0 + (size_t)bz * sA;
    const __nv_bfloat16* Apl1 = A1 + (size_t)bz * sA;
    const __nv_bfloat16* Bpl0 = B0 + (size_t)bz * sB;
    const __nv_bfloat16* Bpl1 = B1 + (size_t)bz * sB;
    const int bm = blockIdx.y * 128, bn = blockIdx.x * 128;
    const int nch = K >> 4;

    const int lr0 = tid >> 1, lks0 = tid & 1;
    const uint32_t so0 = tile_off(lr0, lks0);

    const int j01 = (lane >> 3) & 1;
    const int j23 = lane >> 4;
    const int lr  = lane & 7;
    const int wm = (wid & 3) * 32;
    const int wn = (wid >> 2) * 64;
    uint32_t aoff[2], boff[4];
    #pragma unroll
    for (int mf = 0; mf < 2; ++mf)
        aoff[mf] = tile_off(wm + mf * 16 + j01 * 8 + lr, j23);
    #pragma unroll
    for (int nf2 = 0; nf2 < 4; ++nf2)
        boff[nf2] = tile_off(wn + nf2 * 16 + j23 * 8 + lr, j01);

    float acc[2][8][4];
    #pragma unroll
    for (int mf = 0; mf < 2; ++mf)
        #pragma unroll
        for (int nf = 0; nf < 8; ++nf)
            #pragma unroll
            for (int q = 0; q < 4; ++q) acc[mf][nf][q] = 0.f;

    #pragma unroll 1
    for (int pc = 0; pc < 2 && pc < nch; ++pc) {
        uint32_t base = sbase + (uint32_t)pc * 16384u;
        int k0 = pc << 4;
        size_t gA = (size_t)(bm + lr0) * K + k0 + lks0 * 8;
        size_t gB = (size_t)(bn + lr0) * K + k0 + lks0 * 8;
        CP_ASYNC16(base + so0,         Apl0 + gA);
        CP_ASYNC16(base + 4096 + so0,  Apl1 + gA);
        CP_ASYNC16(base + 8192 + so0,  Bpl0 + gB);
        CP_ASYNC16(base + 12288 + so0, Bpl1 + gB);
        CP_COMMIT();
    }

    for (int c = 0; c < nch; ++c) {
        if (c + 1 < nch) { CP_WAIT1(); } else { CP_WAIT0(); }
        __syncthreads();
        const uint32_t base = sbase + (uint32_t)(c & 1) * 16384u;
        uint32_t af[2][2][4];
        #pragma unroll
        for (int mf = 0; mf < 2; ++mf) {
            LDSM4(af[0][mf][0], af[0][mf][1], af[0][mf][2], af[0][mf][3],
                  base + aoff[mf]);
            LDSM4(af[1][mf][0], af[1][mf][1], af[1][mf][2], af[1][mf][3],
                  base + 4096 + aoff[mf]);
        }
        // B split 0: products a0*b0 and a1*b0
        {
            uint32_t bf[8][2];
            #pragma unroll
            for (int nf2 = 0; nf2 < 4; ++nf2) {
                uint32_t r0, r1, r2, r3;
                LDSM4(r0, r1, r2, r3, base + 8192 + boff[nf2]);
                bf[nf2*2][0] = r0;   bf[nf2*2][1] = r1;
                bf[nf2*2+1][0] = r2; bf[nf2*2+1][1] = r3;
            }
            #pragma unroll
            for (int mf = 0; mf < 2; ++mf)
                #pragma unroll
                for (int nf = 0; nf < 8; ++nf) {
                    MMA16816(acc[mf][nf], af[0][mf], bf[nf]);
                    MMA16816(acc[mf][nf], af[1][mf], bf[nf]);
                }
        }
        // B split 1: product a0*b1
        {
            uint32_t bf[8][2];
            #pragma unroll
            for (int nf2 = 0; nf2 < 4; ++nf2) {
                uint32_t r0, r1, r2, r3;
                LDSM4(r0, r1, r2, r3, base + 12288 + boff[nf2]);
                bf[nf2*2][0] = r0;   bf[nf2*2][1] = r1;
                bf[nf2*2+1][0] = r2; bf[nf2*2+1][1] = r3;
            }
            #pragma unroll
            for (int mf = 0; mf < 2; ++mf)
                #pragma unroll
                for (int nf = 0; nf < 8; ++nf)
                    MMA16816(acc[mf][nf], af[0][mf], bf[nf]);
        }
        __syncthreads();
        if (c + 2 < nch) {
            uint32_t b2 = sbase + (uint32_t)(c & 1) * 16384u;
            int k0 = (c + 2) << 4;
            size_t gA = (size_t)(bm + lr0) * K + k0 + lks0 * 8;
            size_t gB = (size_t)(bn + lr0) * K + k0 + lks0 * 8;
            CP_ASYNC16(b2 + so0,         Apl0 + gA);
            CP_ASYNC16(b2 + 4096 + so0,  Apl1 + gA);
            CP_ASYNC16(b2 + 8192 + so0,  Bpl0 + gB);
            CP_ASYNC16(b2 + 12288 + so0, Bpl1 + gB);
            CP_COMMIT();
        }
    }

    // epilogue: fp32 C, or fused hi/lo bf16 split
    const int er = lane >> 2, ec = (lane & 3) * 2;
    if (D0) {
        __nv_bfloat16* d0 = D0 + (size_t)bz * sC;
        __nv_bfloat16* d1 = D1 + (size_t)bz * sC;
        #pragma unroll
        for (int mf = 0; mf < 2; ++mf)
            #pragma unroll
            for (int nf = 0; nf < 8; ++nf) {
                int row = bm + wm + mf * 16 + er;
                int col = bn + wn + nf * 8 + ec;
                #pragma unroll
                for (int h = 0; h < 2; ++h) {
                    float vx = acc[mf][nf][h*2]   * alpha;
                    float vy = acc[mf][nf][h*2+1] * alpha;
                    __nv_bfloat16 hx = __float2bfloat16(vx);
                    __nv_bfloat16 hy = __float2bfloat16(vy);
                    __nv_bfloat16 lx = __float2bfloat16(vx - __bfloat162float(hx));
                    __nv_bfloat16 ly = __float2bfloat16(vy - __bfloat162float(hy));
                    size_t o = (size_t)(row + h * 8) * ldc + col;
                    *(__nv_bfloat162*)(d0 + o) = __nv_bfloat162(hx, hy);
                    *(__nv_bfloat162*)(d1 + o) = __nv_bfloat162(lx, ly);
                }
            }
    } else {
        float* Cp = C + (size_t)bz * sC;
        #pragma unroll
        for (int mf = 0; mf < 2; ++mf)
            #pragma unroll
            for (int nf = 0; nf < 8; ++nf) {
                int row = bm + wm + mf * 16 + er;
                int col = bn + wn + nf * 8 + ec;
                float bx = 0.f, by = 0.f;
                if (bias) { bx = bias[col]; by = bias[col + 1]; }
                float2 v0 = { acc[mf][nf][0] * alpha + bx, acc[mf][nf][1] * alpha + by };
                float2 v1 = { acc[mf][nf][2] * alpha + bx, acc[mf][nf][3] * alpha + by };
                *(float2*)(Cp + (size_t)row * ldc + col) = v0;
                *(float2*)(Cp + (size_t)(row + 8) * ldc + col) = v1;
            }
    }
}

// ======================= split / transpose-split (2-way) =======================
__global__ void split_kernel(const float* __restrict__ src,
                             __nv_bfloat16* __restrict__ d0,
                             __nv_bfloat16* __restrict__ d1, size_t n4)
{
    for (size_t i = (size_t)blockIdx.x * 256 + threadIdx.x; i < n4;
         i += (size_t)gridDim.x * 256) {
        float4 v = ((const float4*)src)[i];
        float vv[4] = { v.x, v.y, v.z, v.w };
        __nv_bfloat16 h0[4], h1[4];
        #pragma unroll
        for (int t = 0; t < 4; t++) {
            h0[t] = __float2bfloat16(vv[t]);
            h1[t] = __float2bfloat16(vv[t] - __bfloat162float(h0[t]));
        }
        ((__nv_bfloat162*)d0)[2*i]   = __nv_bfloat162(h0[0], h0[1]);
        ((__nv_bfloat162*)d0)[2*i+1] = __nv_bfloat162(h0[2], h0[3]);
        ((__nv_bfloat162*)d1)[2*i]   = __nv_bfloat162(h1[0], h1[1]);
        ((__nv_bfloat162*)d1)[2*i+1] = __nv_bfloat162(h1[2], h1[3]);
    }
}

__global__ void tsplit_kernel(const float* __restrict__ src, int ld, size_t sSrc,
                              const float* __restrict__ mask,
                              __nv_bfloat16* __restrict__ d0,
                              __nv_bfloat16* __restrict__ d1)
{
    __shared__ float tile[32][33];
    int bz = blockIdx.z;
    src += (size_t)bz * sSrc;
    const float* mk = mask ? (mask + (size_t)bz * S_) : nullptr;
    __nv_bfloat16* p0 = d0 + (size_t)bz * E_ * S_;
    __nv_bfloat16* p1 = d1 + (size_t)bz * E_ * S_;
    int e0 = blockIdx.x * 32, s0 = blockIdx.y * 32;
    int tx = threadIdx.x & 31, ty = threadIdx.x >> 5;
    #pragma unroll
    for (int i = ty; i < 32; i += 8) {
        float v = src[(size_t)(s0 + i) * ld + e0 + tx];
        if (mk) v *= mk[s0 + i];
        tile[i][tx] = v;
    }
    __syncthreads();
    #pragma unroll
    for (int i = ty; i < 32; i += 8) {
        float v = tile[tx][i];
        __nv_bfloat16 h = __float2bfloat16(v);
        __nv_bfloat16 l = __float2bfloat16(v - __bfloat162float(h));
        p0[(size_t)(e0 + i) * S_ + s0 + tx] = h;
        p1[(size_t)(e0 + i) * S_ + s0 + tx] = l;
    }
}

// ======================= norms =======================
__global__ void tile_norms_kernel() {
    int idx = blockIdx.x * 256 + threadIdx.x;
    int which = idx / (B_ * NTILE);
    int rem   = idx % (B_ * NTILE);
    int b = rem / NTILE, t = rem % NTILE;
    int s2 = t / (E_ / 2), d2 = t % (E_ / 2);
    const float* p = g_qkv + (size_t)(b * S_ + 2 * s2) * QKV_LD + which * E_ + 2 * d2;
    float v00 = p[0], v01 = p[1], v10 = p[QKV_LD], v11 = p[QKV_LD + 1];
    float n = sqrtf(v00 * v00 + v01 * v01 + v10 * v10 + v11 * v11);
    (which ? g_norm_k : g_norm_q)[rem] = n;
}

__global__ void wo_norms_kernel(const float* __restrict__ WO) {
    __shared__ float sh[256];
    int row = blockIdx.x;
    const float* p = WO + (size_t)row * E_;
    float s = 0.f;
    for (int i = threadIdx.x; i < E_; i += 256) { float v = p[i]; s += v * v; }
    sh[threadIdx.x] = s; __syncthreads();
    for (int o = 128; o > 0; o >>= 1) {
        if (threadIdx.x < o) sh[threadIdx.x] += sh[threadIdx.x + o];
        __syncthreads();
    }
    if (threadIdx.x == 0) g_norm_wo[row] = sqrtf(sh[0]);
}

// ======================= median via radix select =======================
__global__ void sel_init_kernel() {
    int t = threadIdx.x;
    for (int s = 0; s < NSEL; s++) g_hist[s][t] = 0;
    if (t < NSEL) {
        g_prefix[t] = 0;
        g_kk[t] = (t < 8) ? (NTILE / 2) : (S_ / 2);
        g_cntless[t] = 0;
        g_maxbelow[t] = 0;
    }
}

__global__ void sel_hist_kernel(int round) {
    __shared__ unsigned sh[256];
    int sel = blockIdx.y;
    const float* p; int n; sel_info(sel, &p, &n);
    sh[threadIdx.x] = 0; __syncthreads();
    unsigned himask = (round == 0) ? 0u : (0xFFFFFFFFu << (32 - 8 * round));
    unsigned pref = g_prefix[sel];
    int shift = 24 - 8 * round;
    for (int i = blockIdx.x * 256 + threadIdx.x; i < n; i += gridDim.x * 256) {
        unsigned bits = __float_as_uint(p[i]);
        if ((bits & himask) == pref) atomicAdd(&sh[(bits >> shift) & 255], 1u);
    }
    __syncthreads();
    if (sh[threadIdx.x]) atomicAdd(&g_hist[sel][threadIdx.x], sh[threadIdx.x]);
}

__global__ void sel_scan_kernel(int round) {
    int sel = threadIdx.x;
    if (sel >= NSEL) return;
    int need = g_kk[sel];
    unsigned cum = 0; int bin = 255;
    for (int i = 0; i < 256; i++) {
        unsigned c = g_hist[sel][i];
        if (cum + c > (unsigned)need) { bin = i; break; }
        cum += c;
    }
    g_kk[sel] = need - (int)cum;
    g_prefix[sel] |= ((unsigned)bin) << (24 - 8 * round);
    for (int i = 0; i < 256; i++) g_hist[sel][i] = 0;
}

__global__ void sel_fin1_kernel() {
    __shared__ unsigned scnt, smax;
    int sel = blockIdx.y;
    const float* p; int n; sel_info(sel, &p, &n);
    if (threadIdx.x == 0) { scnt = 0; smax = 0; }
    __syncthreads();
    float bval = __uint_as_float(g_prefix[sel]);
    unsigned cnt = 0, mx = 0;
    for (int i = blockIdx.x * 256 + threadIdx.x; i < n; i += gridDim.x * 256) {
        float v = p[i];
        if (v < bval) { cnt++; unsigned bv = __float_as_uint(v); if (bv > mx) mx = bv; }
    }
    atomicAdd(&scnt, cnt); atomicMax(&smax, mx);
    __syncthreads();
    if (threadIdx.x == 0) {
        if (scnt) atomicAdd(&g_cntless[sel], scnt);
        atomicMax(&g_maxbelow[sel], smax);
    }
}

__global__ void sel_fin2_kernel() {
    int sel = threadIdx.x;
    if (sel >= NSEL) return;
    unsigned kt = (sel < 8) ? (unsigned)(NTILE / 2) : (unsigned)(S_ / 2);
    float b = __uint_as_float(g_prefix[sel]);
    float a = (g_cntless[sel] == kt) ? __uint_as_float(g_maxbelow[sel]) : b;
    g_thr[sel] = 0.5f * (a + b);
}

// ======================= mask application =======================
__global__ void mask_qk_kernel() {
    int idx = blockIdx.x * 256 + threadIdx.x;
    int which = idx / (B_ * NTILE);
    int rem   = idx % (B_ * NTILE);
    int b = rem / NTILE, t = rem % NTILE;
    float n = (which ? g_norm_k : g_norm_q)[rem];
    if (n < g_thr[which * 4 + b]) {
        int s2 = t / (E_ / 2), d2 = t % (E_ / 2);
        float* p = g_qkv + (size_t)(b * S_ + 2 * s2) * QKV_LD + which * E_ + 2 * d2;
        p[0] = 0.f; p[1] = 0.f; p[QKV_LD] = 0.f; p[QKV_LD + 1] = 0.f;
    }
}

__global__ void wmask_kernel() {
    int i = blockIdx.x * 256 + threadIdx.x;
    if (i >= B_ * S_) return;
    int b = i / S_;
    g_wmask[i] = (g_norm_wo[i] >= g_thr[8 + b]) ? 1.f : 0.f;
}

// ======================= launch =======================
extern "C" void kernel_launch(void* const* d_in, const int* in_sizes, int n_in,
                              void* d_out, int out_size)
{
    const float* x    = (const float*)d_in[0];   // [4,2048,1024]
    const float* Wqkv = (const float*)d_in[1];   // [3072,1024]
    const float* bqkv = (const float*)d_in[2];   // [3072]
    const float* WO   = (const float*)d_in[3];   // [4,1,2048,1024]
    float* out        = (float*)d_out;           // [4,2048,1024]
    (void)in_sizes; (void)n_in; (void)out_size;

    float *qkv, *wmask;
    cudaGetSymbolAddress((void**)&qkv,   g_qkv);
    cudaGetSymbolAddress((void**)&wmask, g_wmask);
    __nv_bfloat16 *x0,*x1, *wv0,*wv1, *xT0,*xT1, *qT0,*qT1, *kT0,*kT1,
                  *vT0,*vT1, *oT0,*oT1, *am0,*am1, *h10,*h11, *gt0,*gt1,
                  *tt0,*tt1, *ut0,*ut1;
    cudaGetSymbolAddress((void**)&x0, g_x0); cudaGetSymbolAddress((void**)&x1, g_x1);
    cudaGetSymbolAddress((void**)&wv0, g_wv0); cudaGetSymbolAddress((void**)&wv1, g_wv1);
    cudaGetSymbolAddress((void**)&xT0, g_xT0); cudaGetSymbolAddress((void**)&xT1, g_xT1);
    cudaGetSymbolAddress((void**)&qT0, g_qT0); cudaGetSymbolAddress((void**)&qT1, g_qT1);
    cudaGetSymbolAddress((void**)&kT0, g_kT0); cudaGetSymbolAddress((void**)&kT1, g_kT1);
    cudaGetSymbolAddress((void**)&vT0, g_vT0); cudaGetSymbolAddress((void**)&vT1, g_vT1);
    cudaGetSymbolAddress((void**)&oT0, g_oT0); cudaGetSymbolAddress((void**)&oT1, g_oT1);
    cudaGetSymbolAddress((void**)&am0, g_am0); cudaGetSymbolAddress((void**)&am1, g_am1);
    cudaGetSymbolAddress((void**)&h10, g_h10); cudaGetSymbolAddress((void**)&h11, g_h11);
    cudaGetSymbolAddress((void**)&gt0, g_gt0); cudaGetSymbolAddress((void**)&gt1, g_gt1);
    cudaGetSymbolAddress((void**)&tt0, g_tt0); cudaGetSymbolAddress((void**)&tt1, g_tt1);
    cudaGetSymbolAddress((void**)&ut0, g_ut0); cudaGetSymbolAddress((void**)&ut1, g_ut1);

    const size_t EE = (size_t)E_ * E_;
    const size_t SE = (size_t)S_ * E_;
    const size_t ES = (size_t)E_ * S_;

    // 1) 2-way splits of x and the v-rows of Wqkv
    split_kernel<<<2048, 256>>>(x, x0, x1, B_*SE/4);
    split_kernel<<<2048, 256>>>(Wqkv + 2048 * E_, wv0, wv1, EE/4);

    // 2a) q,k columns: EXACT fp32 SGEMM (bit-identical masks)
    sgemm_nt<<<dim3(2048 / BN, (B_ * S_) / BM, 1), 256>>>(
        x, E_, Wqkv, E_, qkv, QKV_LD, B_ * S_, 2048, E_, bqkv);
    // 2b) v columns: bf16x3 warp-MMA (fp32 out into qkv layout)
    mma_nt<<<dim3(E_/128, (B_*S_)/128, 1), 256>>>(
        x0, x1, 0, wv0, wv1, 0, qkv + 2048, nullptr, nullptr, 0, QKV_LD,
        B_*S_, E_, E_, bqkv + 2048, 1.f);

    // 3) norms + medians + masks (bit-accurate path)
    tile_norms_kernel<<<(2 * B_ * NTILE) / 256, 256>>>();
    wo_norms_kernel<<<B_ * S_, 256>>>(WO);
    sel_init_kernel<<<1, 256>>>();
    for (int r = 0; r < 4; r++) {
        sel_hist_kernel<<<dim3(64, NSEL), 256>>>(r);
        sel_scan_kernel<<<1, 32>>>(r);
    }
    sel_fin1_kernel<<<dim3(64, NSEL), 256>>>();
    sel_fin2_kernel<<<1, 32>>>();
    mask_qk_kernel<<<(2 * B_ * NTILE) / 256, 256>>>();
    wmask_kernel<<<(B_ * S_) / 256, 256>>>();

    // 4) transpose + 2-way split operands for the TN factors
    dim3 tg(E_/32, S_/32, B_);
    tsplit_kernel<<<tg, 256>>>(x, E_, SE, nullptr, xT0, xT1);
    tsplit_kernel<<<tg, 256>>>(qkv + 0,     QKV_LD, (size_t)S_*QKV_LD, nullptr, qT0, qT1);
    tsplit_kernel<<<tg, 256>>>(qkv + E_,    QKV_LD, (size_t)S_*QKV_LD, nullptr, kT0, kT1);
    tsplit_kernel<<<tg, 256>>>(qkv + 2*E_,  QKV_LD, (size_t)S_*QKV_LD, nullptr, vT0, vT1);
    tsplit_kernel<<<tg, 256>>>(WO, E_, SE, wmask, oT0, oT1);

    // 5) E x E factors (bf16x3, K = S); fused hi/lo bf16 epilogue (no fp32 scratch)
    dim3 ge(E_/128, E_/128, B_);
    mma_nt<<<ge, 256>>>(qT0, qT1, ES, kT0, kT1, ES,
                        nullptr, am0, am1, EE, E_, E_, E_, S_, nullptr, 1.f);     // A = Qp^T Kp
    mma_nt<<<ge, 256>>>(xT0, xT1, ES, vT0, vT1, ES,
                        nullptr, h10, h11, EE, E_, E_, E_, S_, nullptr, 1.f);     // H1 = x^T v
    mma_nt<<<ge, 256>>>(xT0, xT1, ES, oT0, oT1, ES,
                        nullptr, gt0, gt1, EE, E_, E_, E_, S_, nullptr, 1.f);     // Gt

    // 6) chain: Tt = Gt * H1^T (NT), Ut = Tt * A^T (NT) / 32  (fused split epilogues)
    mma_nt<<<ge, 256>>>(gt0, gt1, EE, h10, h11, EE,
                        nullptr, tt0, tt1, EE, E_, E_, E_, E_, nullptr, 1.f);     // Tt
    mma_nt<<<ge, 256>>>(tt0, tt1, EE, am0, am1, EE,
                        nullptr, ut0, ut1, EE, E_, E_, E_, E_, nullptr, 1.f / 32.f); // Ut

    // 7) out = x @ U  (NT vs Ut, bf16x3, fp32 out)
    mma_nt<<<dim3(E_/128, S_/128, B_), 256>>>(
        x0, x1, SE, ut0, ut1, EE,
        out, nullptr, nullptr, SE, E_, S_, E_, E_, nullptr, 1.f);
}

// round 13
// speedup vs baseline: 1.8404x; 1.0858x over previous
#include <cuda_runtime.h>
#include <cuda_bf16.h>
#include <stdint.h>

#define B_    4
#define S_    2048
#define E_    1024
#define QKV_LD 3072
#define NTILE ((S_/2)*(E_/2))   // 524288 tiles per (b, q|k)
#define NSEL  12                // 0..3 q-batches, 4..7 k-batches, 8..11 WO-batches

// ======================= PTX helpers =======================
__device__ __forceinline__ uint32_t smem_u32(const void* p) {
    uint32_t a;
    asm("{ .reg .u64 t; cvta.to.shared.u64 t, %1; cvt.u32.u64 %0, t; }" : "=r"(a) : "l"(p));
    return a;
}
#define CP_ASYNC16(s, g) \
    asm volatile("cp.async.cg.shared.global [%0], [%1], 16;" :: "r"(s), "l"(g))
#define CP_COMMIT() asm volatile("cp.async.commit_group;" ::: "memory")
#define CP_WAIT1()  asm volatile("cp.async.wait_group 1;" ::: "memory")
#define CP_WAIT0()  asm volatile("cp.async.wait_group 0;" ::: "memory")
#define LDSM4(r0, r1, r2, r3, a) \
    asm volatile("ldmatrix.sync.aligned.m8n8.x4.shared.b16 {%0,%1,%2,%3}, [%4];" \
        : "=r"(r0), "=r"(r1), "=r"(r2), "=r"(r3) : "r"(a))
#define MMA16816(c, a, b) \
    asm volatile("mma.sync.aligned.m16n8k16.row.col.f32.bf16.bf16.f32 " \
        "{%0,%1,%2,%3}, {%4,%5,%6,%7}, {%8,%9}, {%0,%1,%2,%3};" \
        : "+f"((c)[0]), "+f"((c)[1]), "+f"((c)[2]), "+f"((c)[3]) \
        : "r"((a)[0]), "r"((a)[1]), "r"((a)[2]), "r"((a)[3]), "r"((b)[0]), "r"((b)[1]))

// 8x8-matrix-blocked smem layout for a 128x16 bf16 tile (4 KB)
__device__ __forceinline__ uint32_t tile_off(int row, int ks) {
    return (uint32_t)((((row >> 3) * 2 + ks) * 128) + ((((row & 7) ^ (ks * 2)) & 7) * 16));
}

// ======================= scratch (device globals) =======================
__device__ float g_qkv[B_*S_*QKV_LD];          // [b, s, 3E] fp32
__device__ float g_norm_q[B_*NTILE];
__device__ float g_norm_k[B_*NTILE];
__device__ float g_norm_wo[B_*S_];
__device__ float g_wmask[B_*S_];

// bf16 hi/lo splits
__device__ __nv_bfloat16 g_x0[B_*S_*E_],  g_x1[B_*S_*E_];
__device__ __nv_bfloat16 g_wv0[E_*E_],    g_wv1[E_*E_];    // v rows of Wqkv
__device__ __nv_bfloat16 g_xT0[B_*E_*S_], g_xT1[B_*E_*S_];
__device__ __nv_bfloat16 g_qT0[B_*E_*S_], g_qT1[B_*E_*S_];
__device__ __nv_bfloat16 g_kT0[B_*E_*S_], g_kT1[B_*E_*S_];
__device__ __nv_bfloat16 g_vT0[B_*E_*S_], g_vT1[B_*E_*S_];
__device__ __nv_bfloat16 g_oT0[B_*E_*S_], g_oT1[B_*E_*S_];
__device__ __nv_bfloat16 g_am0[B_*E_*E_], g_am1[B_*E_*E_];
__device__ __nv_bfloat16 g_h10[B_*E_*E_], g_h11[B_*E_*E_];
__device__ __nv_bfloat16 g_gt0[B_*E_*E_], g_gt1[B_*E_*E_];
__device__ __nv_bfloat16 g_tt0[B_*E_*E_], g_tt1[B_*E_*E_];
__device__ __nv_bfloat16 g_ut0[B_*E_*E_], g_ut1[B_*E_*E_];

__device__ unsigned g_hist[NSEL][256];
__device__ unsigned g_prefix[NSEL];
__device__ int      g_kk[NSEL];
__device__ unsigned g_cntless[NSEL];
__device__ unsigned g_maxbelow[NSEL];
__device__ float    g_thr[NSEL];

__device__ __forceinline__ void sel_info(int sel, const float** p, int* n) {
    if (sel < 4)      { *p = g_norm_q  + (size_t)sel * NTILE;       *n = NTILE; }
    else if (sel < 8) { *p = g_norm_k  + (size_t)(sel-4) * NTILE;   *n = NTILE; }
    else              { *p = g_norm_wo + (size_t)(sel-8) * S_;      *n = S_;    }
}

// ======================= fp32 SGEMM (EXACT R2 code, NT) ==============
// Bit-identical to the R2/R11/R12 passing kernels for q,k -> bit-identical masks.
#define BM 128
#define BN 128
#define BKK 16

__global__ void __launch_bounds__(256, 1) sgemm_nt(
    const float* __restrict__ A, int lda,
    const float* __restrict__ B, int ldb,
    float* __restrict__ C, int ldc,
    int M, int N, int K,
    const float* __restrict__ bias)
{
    __shared__ float As[BKK][BM];
    __shared__ float Bs[BKK][BN];
    const int bm = blockIdx.y * BM, bn = blockIdx.x * BN;
    const int tid = threadIdx.x;
    const int tx = tid & 15, ty = tid >> 4;

    float s[8][8];
    #pragma unroll
    for (int i = 0; i < 8; i++)
        #pragma unroll
        for (int j = 0; j < 8; j++) s[i][j] = 0.f;

    for (int k0 = 0; k0 < K; k0 += BKK) {
        #pragma unroll
        for (int i = 0; i < 2; i++) {
            int f = tid + i * 256;
            int r = f >> 2, c4 = f & 3;
            float4 v = *(const float4*)(A + (size_t)(bm + r) * lda + k0 + c4 * 4);
            As[c4 * 4 + 0][r] = v.x; As[c4 * 4 + 1][r] = v.y;
            As[c4 * 4 + 2][r] = v.z; As[c4 * 4 + 3][r] = v.w;
        }
        #pragma unroll
        for (int i = 0; i < 2; i++) {
            int f = tid + i * 256;
            int r = f >> 2, c4 = f & 3;
            float4 v = *(const float4*)(B + (size_t)(bn + r) * ldb + k0 + c4 * 4);
            Bs[c4 * 4 + 0][r] = v.x; Bs[c4 * 4 + 1][r] = v.y;
            Bs[c4 * 4 + 2][r] = v.z; Bs[c4 * 4 + 3][r] = v.w;
        }
        __syncthreads();

        float t[8][8];
        #pragma unroll
        for (int i = 0; i < 8; i++)
            #pragma unroll
            for (int j = 0; j < 8; j++) t[i][j] = 0.f;

        #pragma unroll
        for (int kk = 0; kk < BKK; kk++) {
            float a[8], b[8];
            *(float4*)&a[0] = *(float4*)&As[kk][ty * 8];
            *(float4*)&a[4] = *(float4*)&As[kk][ty * 8 + 4];
            *(float4*)&b[0] = *(float4*)&Bs[kk][tx * 8];
            *(float4*)&b[4] = *(float4*)&Bs[kk][tx * 8 + 4];
            #pragma unroll
            for (int i = 0; i < 8; i++)
                #pragma unroll
                for (int j = 0; j < 8; j++)
                    t[i][j] += a[i] * b[j];
        }
        #pragma unroll
        for (int i = 0; i < 8; i++)
            #pragma unroll
            for (int j = 0; j < 8; j++) s[i][j] += t[i][j];
        __syncthreads();
    }
    #pragma unroll
    for (int i = 0; i < 8; i++) {
        int r = bm + ty * 8 + i;
        #pragma unroll
        for (int j = 0; j < 8; j += 4) {
            int c = bn + tx * 8 + j;
            float4 v = make_float4(s[i][j] * 1.f, s[i][j+1] * 1.f,
                                   s[i][j+2] * 1.f, s[i][j+3] * 1.f);
            if (bias) { v.x += bias[c]; v.y += bias[c+1]; v.z += bias[c+2]; v.w += bias[c+3]; }
            *(float4*)(C + (size_t)r * ldc + c) = v;
        }
    }
}

// ======================= warp-MMA NT GEMM body (bf16x3, fp32 accum) =================
// C[i,j] = alpha * sum_k (A0B0 + A1B0 + A0B1) (+bias[j]). ld of A/B == K (K-major).
// 3-stage cp.async pipeline, ONE __syncthreads per chunk. smem = 3 x 16KB.
// fp32 out (d0==null) or fused hi/lo bf16 split to d0/d1.
__device__ __forceinline__ void mma_body(
    const __nv_bfloat16* __restrict__ Apl0, const __nv_bfloat16* __restrict__ Apl1,
    const __nv_bfloat16* __restrict__ Bpl0, const __nv_bfloat16* __restrict__ Bpl1,
    float* __restrict__ Cp,
    __nv_bfloat16* __restrict__ d0, __nv_bfloat16* __restrict__ d1,
    int ldc, int K, const float* __restrict__ bias, float alpha, uint32_t sbase)
{
    const int tid = threadIdx.x;
    const int wid = tid >> 5, lane = tid & 31;
    const int bm = blockIdx.y * 128, bn = blockIdx.x * 128;
    const int nch = K >> 4;

    const int lr0 = tid >> 1, lks0 = tid & 1;
    const uint32_t so0 = tile_off(lr0, lks0);

    const int j01 = (lane >> 3) & 1;
    const int j23 = lane >> 4;
    const int lr  = lane & 7;
    const int wm = (wid & 3) * 32;
    const int wn = (wid >> 2) * 64;
    uint32_t aoff[2], boff[4];
    #pragma unroll
    for (int mf = 0; mf < 2; ++mf)
        aoff[mf] = tile_off(wm + mf * 16 + j01 * 8 + lr, j23);
    #pragma unroll
    for (int nf2 = 0; nf2 < 4; ++nf2)
        boff[nf2] = tile_off(wn + nf2 * 16 + j23 * 8 + lr, j01);

    float acc[2][8][4];
    #pragma unroll
    for (int mf = 0; mf < 2; ++mf)
        #pragma unroll
        for (int nf = 0; nf < 8; ++nf)
            #pragma unroll
            for (int q = 0; q < 4; ++q) acc[mf][nf][q] = 0.f;

    // prologue: stages 0, 1 into buffers 0, 1
    #pragma unroll 1
    for (int pc = 0; pc < 2; ++pc) {
        uint32_t base = sbase + (uint32_t)pc * 16384u;
        int k0 = pc << 4;
        size_t gA = (size_t)(bm + lr0) * K + k0 + lks0 * 8;
        size_t gB = (size_t)(bn + lr0) * K + k0 + lks0 * 8;
        CP_ASYNC16(base + so0,         Apl0 + gA);
        CP_ASYNC16(base + 4096 + so0,  Apl1 + gA);
        CP_ASYNC16(base + 8192 + so0,  Bpl0 + gB);
        CP_ASYNC16(base + 12288 + so0, Bpl1 + gB);
        CP_COMMIT();
    }

    int buf = 0, ibuf = 2;   // compute buffer, next issue buffer (c+2)%3
    for (int c = 0; c < nch; ++c) {
        if (c + 1 < nch) { CP_WAIT1(); } else { CP_WAIT0(); }
        __syncthreads();   // single barrier per chunk: data visible + buffer (c-1)%3 free
        const uint32_t base = sbase + (uint32_t)buf * 16384u;
        uint32_t af[2][2][4];
        #pragma unroll
        for (int mf = 0; mf < 2; ++mf) {
            LDSM4(af[0][mf][0], af[0][mf][1], af[0][mf][2], af[0][mf][3],
                  base + aoff[mf]);
            LDSM4(af[1][mf][0], af[1][mf][1], af[1][mf][2], af[1][mf][3],
                  base + 4096 + aoff[mf]);
        }
        // B split 0: a0*b0, a1*b0
        {
            uint32_t bf[8][2];
            #pragma unroll
            for (int nf2 = 0; nf2 < 4; ++nf2) {
                uint32_t r0, r1, r2, r3;
                LDSM4(r0, r1, r2, r3, base + 8192 + boff[nf2]);
                bf[nf2*2][0] = r0;   bf[nf2*2][1] = r1;
                bf[nf2*2+1][0] = r2; bf[nf2*2+1][1] = r3;
            }
            #pragma unroll
            for (int mf = 0; mf < 2; ++mf)
                #pragma unroll
                for (int nf = 0; nf < 8; ++nf) {
                    MMA16816(acc[mf][nf], af[0][mf], bf[nf]);
                    MMA16816(acc[mf][nf], af[1][mf], bf[nf]);
                }
        }
        // B split 1: a0*b1
        {
            uint32_t bf[8][2];
            #pragma unroll
            for (int nf2 = 0; nf2 < 4; ++nf2) {
                uint32_t r0, r1, r2, r3;
                LDSM4(r0, r1, r2, r3, base + 12288 + boff[nf2]);
                bf[nf2*2][0] = r0;   bf[nf2*2][1] = r1;
                bf[nf2*2+1][0] = r2; bf[nf2*2+1][1] = r3;
            }
            #pragma unroll
            for (int mf = 0; mf < 2; ++mf)
                #pragma unroll
                for (int nf = 0; nf < 8; ++nf)
                    MMA16816(acc[mf][nf], af[0][mf], bf[nf]);
        }
        // issue stage c+2 into buffer (c+2)%3 == (c-1)%3 — safe: all warps passed
        // this chunk's barrier, so nobody still reads chunk c-1 from that buffer.
        if (c + 2 < nch) {
            uint32_t b2 = sbase + (uint32_t)ibuf * 16384u;
            int k0 = (c + 2) << 4;
            size_t gA = (size_t)(bm + lr0) * K + k0 + lks0 * 8;
            size_t gB = (size_t)(bn + lr0) * K + k0 + lks0 * 8;
            CP_ASYNC16(b2 + so0,         Apl0 + gA);
            CP_ASYNC16(b2 + 4096 + so0,  Apl1 + gA);
            CP_ASYNC16(b2 + 8192 + so0,  Bpl0 + gB);
            CP_ASYNC16(b2 + 12288 + so0, Bpl1 + gB);
            CP_COMMIT();
        }
        buf  = (buf  == 2) ? 0 : buf  + 1;
        ibuf = (ibuf == 2) ? 0 : ibuf + 1;
    }

    const int er = lane >> 2, ec = (lane & 3) * 2;
    if (d0) {
        #pragma unroll
        for (int mf = 0; mf < 2; ++mf)
            #pragma unroll
            for (int nf = 0; nf < 8; ++nf) {
                int row = bm + wm + mf * 16 + er;
                int col = bn + wn + nf * 8 + ec;
                #pragma unroll
                for (int h = 0; h < 2; ++h) {
                    float vx = acc[mf][nf][h*2]   * alpha;
                    float vy = acc[mf][nf][h*2+1] * alpha;
                    __nv_bfloat16 hx = __float2bfloat16(vx);
                    __nv_bfloat16 hy = __float2bfloat16(vy);
                    __nv_bfloat16 lx = __float2bfloat16(vx - __bfloat162float(hx));
                    __nv_bfloat16 ly = __float2bfloat16(vy - __bfloat162float(hy));
                    size_t o = (size_t)(row + h * 8) * ldc + col;
                    *(__nv_bfloat162*)(d0 + o) = __nv_bfloat162(hx, hy);
                    *(__nv_bfloat162*)(d1 + o) = __nv_bfloat162(lx, ly);
                }
            }
    } else {
        #pragma unroll
        for (int mf = 0; mf < 2; ++mf)
            #pragma unroll
            for (int nf = 0; nf < 8; ++nf) {
                int row = bm + wm + mf * 16 + er;
                int col = bn + wn + nf * 8 + ec;
                float bx = 0.f, by = 0.f;
                if (bias) { bx = bias[col]; by = bias[col + 1]; }
                float2 v0 = { acc[mf][nf][0] * alpha + bx, acc[mf][nf][1] * alpha + by };
                float2 v1 = { acc[mf][nf][2] * alpha + bx, acc[mf][nf][3] * alpha + by };
                *(float2*)(Cp + (size_t)row * ldc + col) = v0;
                *(float2*)(Cp + (size_t)(row + 8) * ldc + col) = v1;
            }
    }
}

// generic launcher (batched over z)
__global__ void __launch_bounds__(256, 2) mma_nt(
    const __nv_bfloat16* __restrict__ A0, const __nv_bfloat16* __restrict__ A1, size_t sA,
    const __nv_bfloat16* __restrict__ B0, const __nv_bfloat16* __restrict__ B1, size_t sB,
    float* __restrict__ C,
    __nv_bfloat16* __restrict__ D0, __nv_bfloat16* __restrict__ D1,
    size_t sC, int ldc,
    int K, const float* __restrict__ bias, float alpha)
{
    __shared__ __align__(128) char smem[3 * 16384];
    const int bz = blockIdx.z;
    mma_body(A0 + (size_t)bz * sA, A1 + (size_t)bz * sA,
             B0 + (size_t)bz * sB, B1 + (size_t)bz * sB,
             C ? C + (size_t)bz * sC : nullptr,
             D0 ? D0 + (size_t)bz * sC : nullptr,
             D1 ? D1 + (size_t)bz * sC : nullptr,
             ldc, K, bias, alpha, smem_u32(smem));
}

// merged factor GEMMs: z in 0..11 -> which = z>>2 (A|H1|Gt), b = z&3
__global__ void __launch_bounds__(256, 2) mma_fac3()
{
    __shared__ __align__(128) char smem[3 * 16384];
    const int z = blockIdx.z;
    const int which = z >> 2, b = z & 3;
    const size_t ES = (size_t)E_ * S_;
    const size_t EE = (size_t)E_ * E_;
    const __nv_bfloat16 *A0, *A1, *B0, *B1;
    __nv_bfloat16 *D0, *D1;
    if (which == 0)      { A0 = g_qT0; A1 = g_qT1; B0 = g_kT0; B1 = g_kT1; D0 = g_am0; D1 = g_am1; }
    else if (which == 1) { A0 = g_xT0; A1 = g_xT1; B0 = g_vT0; B1 = g_vT1; D0 = g_h10; D1 = g_h11; }
    else                 { A0 = g_xT0; A1 = g_xT1; B0 = g_oT0; B1 = g_oT1; D0 = g_gt0; D1 = g_gt1; }
    mma_body(A0 + (size_t)b * ES, A1 + (size_t)b * ES,
             B0 + (size_t)b * ES, B1 + (size_t)b * ES,
             nullptr, D0 + (size_t)b * EE, D1 + (size_t)b * EE,
             E_, S_, nullptr, 1.f, smem_u32(smem));
}

// ======================= split / transpose-split (2-way) =======================
__global__ void split_kernel(const float* __restrict__ src,
                             __nv_bfloat16* __restrict__ d0,
                             __nv_bfloat16* __restrict__ d1, size_t n4)
{
    for (size_t i = (size_t)blockIdx.x * 256 + threadIdx.x; i < n4;
         i += (size_t)gridDim.x * 256) {
        float4 v = ((const float4*)src)[i];
        float vv[4] = { v.x, v.y, v.z, v.w };
        __nv_bfloat16 h0[4], h1[4];
        #pragma unroll
        for (int t = 0; t < 4; t++) {
            h0[t] = __float2bfloat16(vv[t]);
            h1[t] = __float2bfloat16(vv[t] - __bfloat162float(h0[t]));
        }
        ((__nv_bfloat162*)d0)[2*i]   = __nv_bfloat162(h0[0], h0[1]);
        ((__nv_bfloat162*)d0)[2*i+1] = __nv_bfloat162(h0[2], h0[3]);
        ((__nv_bfloat162*)d1)[2*i]   = __nv_bfloat162(h1[0], h1[1]);
        ((__nv_bfloat162*)d1)[2*i+1] = __nv_bfloat162(h1[2], h1[3]);
    }
}

// dst[e][s] = src[s][e] * mask; masks: per-row wmask OR fused q/k tile mask
// (norms + threshold; keep = norm >= thr -> identical zeros to the old
// store-then-split path).
__global__ void tsplit_kernel(const float* __restrict__ src, int ld, size_t sSrc,
                              const float* __restrict__ mask,
                              const float* __restrict__ norms, int thr_base,
                              __nv_bfloat16* __restrict__ d0,
                              __nv_bfloat16* __restrict__ d1)
{
    __shared__ float tile[32][33];
    int bz = blockIdx.z;
    src += (size_t)bz * sSrc;
    const float* mk = mask ? (mask + (size_t)bz * S_) : nullptr;
    const float* nm = norms ? (norms + (size_t)bz * NTILE) : nullptr;
    float thr = nm ? g_thr[thr_base + bz] : 0.f;
    __nv_bfloat16* p0 = d0 + (size_t)bz * E_ * S_;
    __nv_bfloat16* p1 = d1 + (size_t)bz * E_ * S_;
    int e0 = blockIdx.x * 32, s0 = blockIdx.y * 32;
    int tx = threadIdx.x & 31, ty = threadIdx.x >> 5;
    #pragma unroll
    for (int i = ty; i < 32; i += 8) {
        int ss = s0 + i, ee = e0 + tx;
        float v = src[(size_t)ss * ld + ee];
        if (mk) v *= mk[ss];
        if (nm) {
            float n = nm[(ss >> 1) * (E_ / 2) + (ee >> 1)];
            if (n < thr) v = 0.f;
        }
        tile[i][tx] = v;
    }
    __syncthreads();
    #pragma unroll
    for (int i = ty; i < 32; i += 8) {
        float v = tile[tx][i];
        __nv_bfloat16 h = __float2bfloat16(v);
        __nv_bfloat16 l = __float2bfloat16(v - __bfloat162float(h));
        p0[(size_t)(e0 + i) * S_ + s0 + tx] = h;
        p1[(size_t)(e0 + i) * S_ + s0 + tx] = l;
    }
}

// ======================= norms =======================
__global__ void tile_norms_kernel() {
    int idx = blockIdx.x * 256 + threadIdx.x;
    int which = idx / (B_ * NTILE);
    int rem   = idx % (B_ * NTILE);
    int b = rem / NTILE, t = rem % NTILE;
    int s2 = t / (E_ / 2), d2 = t % (E_ / 2);
    const float* p = g_qkv + (size_t)(b * S_ + 2 * s2) * QKV_LD + which * E_ + 2 * d2;
    float v00 = p[0], v01 = p[1], v10 = p[QKV_LD], v11 = p[QKV_LD + 1];
    float n = sqrtf(v00 * v00 + v01 * v01 + v10 * v10 + v11 * v11);
    (which ? g_norm_k : g_norm_q)[rem] = n;
}

__global__ void wo_norms_kernel(const float* __restrict__ WO) {
    __shared__ float sh[256];
    int row = blockIdx.x;
    const float* p = WO + (size_t)row * E_;
    float s = 0.f;
    for (int i = threadIdx.x; i < E_; i += 256) { float v = p[i]; s += v * v; }
    sh[threadIdx.x] = s; __syncthreads();
    for (int o = 128; o > 0; o >>= 1) {
        if (threadIdx.x < o) sh[threadIdx.x] += sh[threadIdx.x + o];
        __syncthreads();
    }
    if (threadIdx.x == 0) g_norm_wo[row] = sqrtf(sh[0]);
}

// ======================= median via radix select =======================
__global__ void sel_init_kernel() {
    int t = threadIdx.x;
    for (int s = 0; s < NSEL; s++) g_hist[s][t] = 0;
    if (t < NSEL) {
        g_prefix[t] = 0;
        g_kk[t] = (t < 8) ? (NTILE / 2) : (S_ / 2);
        g_cntless[t] = 0;
        g_maxbelow[t] = 0;
    }
}

__global__ void sel_hist_kernel(int round) {
    __shared__ unsigned sh[256];
    int sel = blockIdx.y;
    const float* p; int n; sel_info(sel, &p, &n);
    sh[threadIdx.x] = 0; __syncthreads();
    unsigned himask = (round == 0) ? 0u : (0xFFFFFFFFu << (32 - 8 * round));
    unsigned pref = g_prefix[sel];
    int shift = 24 - 8 * round;
    for (int i = blockIdx.x * 256 + threadIdx.x; i < n; i += gridDim.x * 256) {
        unsigned bits = __float_as_uint(p[i]);
        if ((bits & himask) == pref) atomicAdd(&sh[(bits >> shift) & 255], 1u);
    }
    __syncthreads();
    if (sh[threadIdx.x]) atomicAdd(&g_hist[sel][threadIdx.x], sh[threadIdx.x]);
}

__global__ void sel_scan_kernel(int round) {
    int sel = threadIdx.x;
    if (sel >= NSEL) return;
    int need = g_kk[sel];
    unsigned cum = 0; int bin = 255;
    for (int i = 0; i < 256; i++) {
        unsigned c = g_hist[sel][i];
        if (cum + c > (unsigned)need) { bin = i; break; }
        cum += c;
    }
    g_kk[sel] = need - (int)cum;
    g_prefix[sel] |= ((unsigned)bin) << (24 - 8 * round);
    for (int i = 0; i < 256; i++) g_hist[sel][i] = 0;
}

__global__ void sel_fin1_kernel() {
    __shared__ unsigned scnt, smax;
    int sel = blockIdx.y;
    const float* p; int n; sel_info(sel, &p, &n);
    if (threadIdx.x == 0) { scnt = 0; smax = 0; }
    __syncthreads();
    float bval = __uint_as_float(g_prefix[sel]);
    unsigned cnt = 0, mx = 0;
    for (int i = blockIdx.x * 256 + threadIdx.x; i < n; i += gridDim.x * 256) {
        float v = p[i];
        if (v < bval) { cnt++; unsigned bv = __float_as_uint(v); if (bv > mx) mx = bv; }
    }
    atomicAdd(&scnt, cnt); atomicMax(&smax, mx);
    __syncthreads();
    if (threadIdx.x == 0) {
        if (scnt) atomicAdd(&g_cntless[sel], scnt);
        atomicMax(&g_maxbelow[sel], smax);
    }
}

__global__ void sel_fin2_kernel() {
    int sel = threadIdx.x;
    if (sel >= NSEL) return;
    unsigned kt = (sel < 8) ? (unsigned)(NTILE / 2) : (unsigned)(S_ / 2);
    float b = __uint_as_float(g_prefix[sel]);
    float a = (g_cntless[sel] == kt) ? __uint_as_float(g_maxbelow[sel]) : b;
    g_thr[sel] = 0.5f * (a + b);
}

__global__ void wmask_kernel() {
    int i = blockIdx.x * 256 + threadIdx.x;
    if (i >= B_ * S_) return;
    int b = i / S_;
    g_wmask[i] = (g_norm_wo[i] >= g_thr[8 + b]) ? 1.f : 0.f;
}

// ======================= launch =======================
extern "C" void kernel_launch(void* const* d_in, const int* in_sizes, int n_in,
                              void* d_out, int out_size)
{
    const float* x    = (const float*)d_in[0];   // [4,2048,1024]
    const float* Wqkv = (const float*)d_in[1];   // [3072,1024]
    const float* bqkv = (const float*)d_in[2];   // [3072]
    const float* WO   = (const float*)d_in[3];   // [4,1,2048,1024]
    float* out        = (float*)d_out;           // [4,2048,1024]
    (void)in_sizes; (void)n_in; (void)out_size;

    float *qkv, *wmask, *nq, *nk;
    cudaGetSymbolAddress((void**)&qkv,   g_qkv);
    cudaGetSymbolAddress((void**)&wmask, g_wmask);
    cudaGetSymbolAddress((void**)&nq,    g_norm_q);
    cudaGetSymbolAddress((void**)&nk,    g_norm_k);
    __nv_bfloat16 *x0,*x1, *wv0,*wv1, *xT0,*xT1, *qT0,*qT1, *kT0,*kT1,
                  *vT0,*vT1, *oT0,*oT1, *am0,*am1, *h10,*h11, *gt0,*gt1,
                  *tt0,*tt1, *ut0,*ut1;
    cudaGetSymbolAddress((void**)&x0, g_x0); cudaGetSymbolAddress((void**)&x1, g_x1);
    cudaGetSymbolAddress((void**)&wv0, g_wv0); cudaGetSymbolAddress((void**)&wv1, g_wv1);
    cudaGetSymbolAddress((void**)&xT0, g_xT0); cudaGetSymbolAddress((void**)&xT1, g_xT1);
    cudaGetSymbolAddress((void**)&qT0, g_qT0); cudaGetSymbolAddress((void**)&qT1, g_qT1);
    cudaGetSymbolAddress((void**)&kT0, g_kT0); cudaGetSymbolAddress((void**)&kT1, g_kT1);
    cudaGetSymbolAddress((void**)&vT0, g_vT0); cudaGetSymbolAddress((void**)&vT1, g_vT1);
    cudaGetSymbolAddress((void**)&oT0, g_oT0); cudaGetSymbolAddress((void**)&oT1, g_oT1);
    cudaGetSymbolAddress((void**)&am0, g_am0); cudaGetSymbolAddress((void**)&am1, g_am1);
    cudaGetSymbolAddress((void**)&h10, g_h10); cudaGetSymbolAddress((void**)&h11, g_h11);
    cudaGetSymbolAddress((void**)&gt0, g_gt0); cudaGetSymbolAddress((void**)&gt1, g_gt1);
    cudaGetSymbolAddress((void**)&tt0, g_tt0); cudaGetSymbolAddress((void**)&tt1, g_tt1);
    cudaGetSymbolAddress((void**)&ut0, g_ut0); cudaGetSymbolAddress((void**)&ut1, g_ut1);

    const size_t EE = (size_t)E_ * E_;
    const size_t SE = (size_t)S_ * E_;

    // 1) 2-way splits of x and the v-rows of Wqkv
    split_kernel<<<2048, 256>>>(x, x0, x1, B_*SE/4);
    split_kernel<<<2048, 256>>>(Wqkv + 2048 * E_, wv0, wv1, EE/4);

    // 2a) q,k columns: EXACT fp32 SGEMM (bit-identical masks)
    sgemm_nt<<<dim3(2048 / BN, (B_ * S_) / BM, 1), 256>>>(
        x, E_, Wqkv, E_, qkv, QKV_LD, B_ * S_, 2048, E_, bqkv);
    // 2b) v columns: bf16x3 warp-MMA (fp32 out into qkv layout)
    mma_nt<<<dim3(E_/128, (B_*S_)/128, 1), 256>>>(
        x0, x1, 0, wv0, wv1, 0, qkv + 2048, nullptr, nullptr, 0, QKV_LD,
        E_, bqkv + 2048, 1.f);

    // 3) norms + medians (bit-accurate path)
    tile_norms_kernel<<<(2 * B_ * NTILE) / 256, 256>>>();
    wo_norms_kernel<<<B_ * S_, 256>>>(WO);
    sel_init_kernel<<<1, 256>>>();
    for (int r = 0; r < 4; r++) {
        sel_hist_kernel<<<dim3(64, NSEL), 256>>>(r);
        sel_scan_kernel<<<1, 32>>>(r);
    }
    sel_fin1_kernel<<<dim3(64, NSEL), 256>>>();
    sel_fin2_kernel<<<1, 32>>>();
    wmask_kernel<<<(B_ * S_) / 256, 256>>>();

    // 4) transpose + 2-way split; q/k tile masks fused in (identical zeros)
    dim3 tg(E_/32, S_/32, B_);
    tsplit_kernel<<<tg, 256>>>(x, E_, SE, nullptr, nullptr, 0, xT0, xT1);
    tsplit_kernel<<<tg, 256>>>(qkv + 0,    QKV_LD, (size_t)S_*QKV_LD, nullptr, nq, 0, qT0, qT1);
    tsplit_kernel<<<tg, 256>>>(qkv + E_,   QKV_LD, (size_t)S_*QKV_LD, nullptr, nk, 4, kT0, kT1);
    tsplit_kernel<<<tg, 256>>>(qkv + 2*E_, QKV_LD, (size_t)S_*QKV_LD, nullptr, nullptr, 0, vT0, vT1);
    tsplit_kernel<<<tg, 256>>>(WO, E_, SE, wmask, nullptr, 0, oT0, oT1);

    // 5) merged E x E factors (A = Qp^T Kp, H1 = x^T v, Gt = (WO_^T x)^T)
    mma_fac3<<<dim3(E_/128, E_/128, 12), 256>>>();

    // 6) chain: Tt = Gt * H1^T (NT), Ut = Tt * A^T (NT) / 32
    dim3 ge(E_/128, E_/128, B_);
    mma_nt<<<ge, 256>>>(gt0, gt1, EE, h10, h11, EE,
                        nullptr, tt0, tt1, EE, E_, E_, nullptr, 1.f);
    mma_nt<<<ge, 256>>>(tt0, tt1, EE, am0, am1, EE,
                        nullptr, ut0, ut1, EE, E_, E_, nullptr, 1.f / 32.f);

    // 7) out = x @ U  (NT vs Ut, fp32 out)
    mma_nt<<<dim3(E_/128, S_/128, B_), 256>>>(
        x0, x1, SE, ut0, ut1, EE,
        out, nullptr, nullptr, SE, E_, E_, nullptr, 1.f);
}

// round 14
// speedup vs baseline: 1.9962x; 1.0846x over previous
#include <cuda_runtime.h>
#include <cuda_bf16.h>
#include <stdint.h>

#define B_    4
#define S_    2048
#define E_    1024
#define QKV_LD 3072
#define NTILE ((S_/2)*(E_/2))   // 524288 tiles per (b, q|k)
#define NSEL  12                // storage; batched radix now uses 0..7 (q,k) only

// ======================= PTX helpers =======================
__device__ __forceinline__ uint32_t smem_u32(const void* p) {
    uint32_t a;
    asm("{ .reg .u64 t; cvta.to.shared.u64 t, %1; cvt.u32.u64 %0, t; }" : "=r"(a) : "l"(p));
    return a;
}
#define CP_ASYNC16(s, g) \
    asm volatile("cp.async.cg.shared.global [%0], [%1], 16;" :: "r"(s), "l"(g))
#define CP_COMMIT() asm volatile("cp.async.commit_group;" ::: "memory")
#define CP_WAIT1()  asm volatile("cp.async.wait_group 1;" ::: "memory")
#define CP_WAIT0()  asm volatile("cp.async.wait_group 0;" ::: "memory")
#define LDSM4(r0, r1, r2, r3, a) \
    asm volatile("ldmatrix.sync.aligned.m8n8.x4.shared.b16 {%0,%1,%2,%3}, [%4];" \
        : "=r"(r0), "=r"(r1), "=r"(r2), "=r"(r3) : "r"(a))
#define MMA16816(c, a, b) \
    asm volatile("mma.sync.aligned.m16n8k16.row.col.f32.bf16.bf16.f32 " \
        "{%0,%1,%2,%3}, {%4,%5,%6,%7}, {%8,%9}, {%0,%1,%2,%3};" \
        : "+f"((c)[0]), "+f"((c)[1]), "+f"((c)[2]), "+f"((c)[3]) \
        : "r"((a)[0]), "r"((a)[1]), "r"((a)[2]), "r"((a)[3]), "r"((b)[0]), "r"((b)[1]))

// 8x8-matrix-blocked smem layout for a 128x16 bf16 tile (4 KB)
__device__ __forceinline__ uint32_t tile_off(int row, int ks) {
    return (uint32_t)((((row >> 3) * 2 + ks) * 128) + ((((row & 7) ^ (ks * 2)) & 7) * 16));
}

// ======================= scratch (device globals) =======================
__device__ float g_qkv[B_*S_*QKV_LD];          // [b, s, 3E] fp32
__device__ float g_norm_q[B_*NTILE];
__device__ float g_norm_k[B_*NTILE];
__device__ float g_norm_wo[B_*S_];
__device__ float g_wmask[B_*S_];

// bf16 hi/lo splits
__device__ __nv_bfloat16 g_x0[B_*S_*E_],  g_x1[B_*S_*E_];
__device__ __nv_bfloat16 g_wv0[E_*E_],    g_wv1[E_*E_];    // v rows of Wqkv
__device__ __nv_bfloat16 g_xT0[B_*E_*S_], g_xT1[B_*E_*S_];
__device__ __nv_bfloat16 g_qT0[B_*E_*S_], g_qT1[B_*E_*S_];
__device__ __nv_bfloat16 g_kT0[B_*E_*S_], g_kT1[B_*E_*S_];
__device__ __nv_bfloat16 g_vT0[B_*E_*S_], g_vT1[B_*E_*S_];
__device__ __nv_bfloat16 g_oT0[B_*E_*S_], g_oT1[B_*E_*S_];
__device__ __nv_bfloat16 g_am0[B_*E_*E_], g_am1[B_*E_*E_];
__device__ __nv_bfloat16 g_h10[B_*E_*E_], g_h11[B_*E_*E_];
__device__ __nv_bfloat16 g_gt0[B_*E_*E_], g_gt1[B_*E_*E_];
__device__ __nv_bfloat16 g_tt0[B_*E_*E_], g_tt1[B_*E_*E_];
__device__ __nv_bfloat16 g_ut0[B_*E_*E_], g_ut1[B_*E_*E_];

__device__ unsigned g_hist[NSEL][256];
__device__ unsigned g_prefix[NSEL];
__device__ int      g_kk[NSEL];
__device__ unsigned g_cntless[NSEL];
__device__ unsigned g_maxbelow[NSEL];
__device__ float    g_thr[NSEL];

__device__ __forceinline__ void sel_info(int sel, const float** p, int* n) {
    if (sel < 4) { *p = g_norm_q + (size_t)sel * NTILE;       *n = NTILE; }
    else         { *p = g_norm_k + (size_t)(sel-4) * NTILE;   *n = NTILE; }
}

// ======================= fp32 SGEMM (EXACT R2 code, NT) ==============
// Bit-identical to the passing kernels for q,k -> bit-identical masks.
#define BM 128
#define BN 128
#define BKK 16

__global__ void __launch_bounds__(256, 1) sgemm_nt(
    const float* __restrict__ A, int lda,
    const float* __restrict__ B, int ldb,
    float* __restrict__ C, int ldc,
    int M, int N, int K,
    const float* __restrict__ bias)
{
    __shared__ float As[BKK][BM];
    __shared__ float Bs[BKK][BN];
    const int bm = blockIdx.y * BM, bn = blockIdx.x * BN;
    const int tid = threadIdx.x;
    const int tx = tid & 15, ty = tid >> 4;

    float s[8][8];
    #pragma unroll
    for (int i = 0; i < 8; i++)
        #pragma unroll
        for (int j = 0; j < 8; j++) s[i][j] = 0.f;

    for (int k0 = 0; k0 < K; k0 += BKK) {
        #pragma unroll
        for (int i = 0; i < 2; i++) {
            int f = tid + i * 256;
            int r = f >> 2, c4 = f & 3;
            float4 v = *(const float4*)(A + (size_t)(bm + r) * lda + k0 + c4 * 4);
            As[c4 * 4 + 0][r] = v.x; As[c4 * 4 + 1][r] = v.y;
            As[c4 * 4 + 2][r] = v.z; As[c4 * 4 + 3][r] = v.w;
        }
        #pragma unroll
        for (int i = 0; i < 2; i++) {
            int f = tid + i * 256;
            int r = f >> 2, c4 = f & 3;
            float4 v = *(const float4*)(B + (size_t)(bn + r) * ldb + k0 + c4 * 4);
            Bs[c4 * 4 + 0][r] = v.x; Bs[c4 * 4 + 1][r] = v.y;
            Bs[c4 * 4 + 2][r] = v.z; Bs[c4 * 4 + 3][r] = v.w;
        }
        __syncthreads();

        float t[8][8];
        #pragma unroll
        for (int i = 0; i < 8; i++)
            #pragma unroll
            for (int j = 0; j < 8; j++) t[i][j] = 0.f;

        #pragma unroll
        for (int kk = 0; kk < BKK; kk++) {
            float a[8], b[8];
            *(float4*)&a[0] = *(float4*)&As[kk][ty * 8];
            *(float4*)&a[4] = *(float4*)&As[kk][ty * 8 + 4];
            *(float4*)&b[0] = *(float4*)&Bs[kk][tx * 8];
            *(float4*)&b[4] = *(float4*)&Bs[kk][tx * 8 + 4];
            #pragma unroll
            for (int i = 0; i < 8; i++)
                #pragma unroll
                for (int j = 0; j < 8; j++)
                    t[i][j] += a[i] * b[j];
        }
        #pragma unroll
        for (int i = 0; i < 8; i++)
            #pragma unroll
            for (int j = 0; j < 8; j++) s[i][j] += t[i][j];
        __syncthreads();
    }
    #pragma unroll
    for (int i = 0; i < 8; i++) {
        int r = bm + ty * 8 + i;
        #pragma unroll
        for (int j = 0; j < 8; j += 4) {
            int c = bn + tx * 8 + j;
            float4 v = make_float4(s[i][j] * 1.f, s[i][j+1] * 1.f,
                                   s[i][j+2] * 1.f, s[i][j+3] * 1.f);
            if (bias) { v.x += bias[c]; v.y += bias[c+1]; v.z += bias[c+2]; v.w += bias[c+3]; }
            *(float4*)(C + (size_t)r * ldc + c) = v;
        }
    }
}

// ======================= warp-MMA NT GEMM body (bf16x3, fp32 accum) =================
__device__ __forceinline__ void mma_body(
    const __nv_bfloat16* __restrict__ Apl0, const __nv_bfloat16* __restrict__ Apl1,
    const __nv_bfloat16* __restrict__ Bpl0, const __nv_bfloat16* __restrict__ Bpl1,
    float* __restrict__ Cp,
    __nv_bfloat16* __restrict__ d0, __nv_bfloat16* __restrict__ d1,
    int ldc, int K, const float* __restrict__ bias, float alpha, uint32_t sbase)
{
    const int tid = threadIdx.x;
    const int wid = tid >> 5, lane = tid & 31;
    const int bm = blockIdx.y * 128, bn = blockIdx.x * 128;
    const int nch = K >> 4;

    const int lr0 = tid >> 1, lks0 = tid & 1;
    const uint32_t so0 = tile_off(lr0, lks0);

    const int j01 = (lane >> 3) & 1;
    const int j23 = lane >> 4;
    const int lr  = lane & 7;
    const int wm = (wid & 3) * 32;
    const int wn = (wid >> 2) * 64;
    uint32_t aoff[2], boff[4];
    #pragma unroll
    for (int mf = 0; mf < 2; ++mf)
        aoff[mf] = tile_off(wm + mf * 16 + j01 * 8 + lr, j23);
    #pragma unroll
    for (int nf2 = 0; nf2 < 4; ++nf2)
        boff[nf2] = tile_off(wn + nf2 * 16 + j23 * 8 + lr, j01);

    float acc[2][8][4];
    #pragma unroll
    for (int mf = 0; mf < 2; ++mf)
        #pragma unroll
        for (int nf = 0; nf < 8; ++nf)
            #pragma unroll
            for (int q = 0; q < 4; ++q) acc[mf][nf][q] = 0.f;

    #pragma unroll 1
    for (int pc = 0; pc < 2; ++pc) {
        uint32_t base = sbase + (uint32_t)pc * 16384u;
        int k0 = pc << 4;
        size_t gA = (size_t)(bm + lr0) * K + k0 + lks0 * 8;
        size_t gB = (size_t)(bn + lr0) * K + k0 + lks0 * 8;
        CP_ASYNC16(base + so0,         Apl0 + gA);
        CP_ASYNC16(base + 4096 + so0,  Apl1 + gA);
        CP_ASYNC16(base + 8192 + so0,  Bpl0 + gB);
        CP_ASYNC16(base + 12288 + so0, Bpl1 + gB);
        CP_COMMIT();
    }

    int buf = 0, ibuf = 2;
    for (int c = 0; c < nch; ++c) {
        if (c + 1 < nch) { CP_WAIT1(); } else { CP_WAIT0(); }
        __syncthreads();
        const uint32_t base = sbase + (uint32_t)buf * 16384u;
        uint32_t af[2][2][4];
        #pragma unroll
        for (int mf = 0; mf < 2; ++mf) {
            LDSM4(af[0][mf][0], af[0][mf][1], af[0][mf][2], af[0][mf][3],
                  base + aoff[mf]);
            LDSM4(af[1][mf][0], af[1][mf][1], af[1][mf][2], af[1][mf][3],
                  base + 4096 + aoff[mf]);
        }
        {
            uint32_t bf[8][2];
            #pragma unroll
            for (int nf2 = 0; nf2 < 4; ++nf2) {
                uint32_t r0, r1, r2, r3;
                LDSM4(r0, r1, r2, r3, base + 8192 + boff[nf2]);
                bf[nf2*2][0] = r0;   bf[nf2*2][1] = r1;
                bf[nf2*2+1][0] = r2; bf[nf2*2+1][1] = r3;
            }
            #pragma unroll
            for (int mf = 0; mf < 2; ++mf)
                #pragma unroll
                for (int nf = 0; nf < 8; ++nf) {
                    MMA16816(acc[mf][nf], af[0][mf], bf[nf]);
                    MMA16816(acc[mf][nf], af[1][mf], bf[nf]);
                }
        }
        {
            uint32_t bf[8][2];
            #pragma unroll
            for (int nf2 = 0; nf2 < 4; ++nf2) {
                uint32_t r0, r1, r2, r3;
                LDSM4(r0, r1, r2, r3, base + 12288 + boff[nf2]);
                bf[nf2*2][0] = r0;   bf[nf2*2][1] = r1;
                bf[nf2*2+1][0] = r2; bf[nf2*2+1][1] = r3;
            }
            #pragma unroll
            for (int mf = 0; mf < 2; ++mf)
                #pragma unroll
                for (int nf = 0; nf < 8; ++nf)
                    MMA16816(acc[mf][nf], af[0][mf], bf[nf]);
        }
        if (c + 2 < nch) {
            uint32_t b2 = sbase + (uint32_t)ibuf * 16384u;
            int k0 = (c + 2) << 4;
            size_t gA = (size_t)(bm + lr0) * K + k0 + lks0 * 8;
            size_t gB = (size_t)(bn + lr0) * K + k0 + lks0 * 8;
            CP_ASYNC16(b2 + so0,         Apl0 + gA);
            CP_ASYNC16(b2 + 4096 + so0,  Apl1 + gA);
            CP_ASYNC16(b2 + 8192 + so0,  Bpl0 + gB);
            CP_ASYNC16(b2 + 12288 + so0, Bpl1 + gB);
            CP_COMMIT();
        }
        buf  = (buf  == 2) ? 0 : buf  + 1;
        ibuf = (ibuf == 2) ? 0 : ibuf + 1;
    }

    const int er = lane >> 2, ec = (lane & 3) * 2;
    if (d0) {
        #pragma unroll
        for (int mf = 0; mf < 2; ++mf)
            #pragma unroll
            for (int nf = 0; nf < 8; ++nf) {
                int row = bm + wm + mf * 16 + er;
                int col = bn + wn + nf * 8 + ec;
                #pragma unroll
                for (int h = 0; h < 2; ++h) {
                    float vx = acc[mf][nf][h*2]   * alpha;
                    float vy = acc[mf][nf][h*2+1] * alpha;
                    __nv_bfloat16 hx = __float2bfloat16(vx);
                    __nv_bfloat16 hy = __float2bfloat16(vy);
                    __nv_bfloat16 lx = __float2bfloat16(vx - __bfloat162float(hx));
                    __nv_bfloat16 ly = __float2bfloat16(vy - __bfloat162float(hy));
                    size_t o = (size_t)(row + h * 8) * ldc + col;
                    *(__nv_bfloat162*)(d0 + o) = __nv_bfloat162(hx, hy);
                    *(__nv_bfloat162*)(d1 + o) = __nv_bfloat162(lx, ly);
                }
            }
    } else {
        #pragma unroll
        for (int mf = 0; mf < 2; ++mf)
            #pragma unroll
            for (int nf = 0; nf < 8; ++nf) {
                int row = bm + wm + mf * 16 + er;
                int col = bn + wn + nf * 8 + ec;
                float bx = 0.f, by = 0.f;
                if (bias) { bx = bias[col]; by = bias[col + 1]; }
                float2 v0 = { acc[mf][nf][0] * alpha + bx, acc[mf][nf][1] * alpha + by };
                float2 v1 = { acc[mf][nf][2] * alpha + bx, acc[mf][nf][3] * alpha + by };
                *(float2*)(Cp + (size_t)row * ldc + col) = v0;
                *(float2*)(Cp + (size_t)(row + 8) * ldc + col) = v1;
            }
    }
}

__global__ void __launch_bounds__(256, 2) mma_nt(
    const __nv_bfloat16* __restrict__ A0, const __nv_bfloat16* __restrict__ A1, size_t sA,
    const __nv_bfloat16* __restrict__ B0, const __nv_bfloat16* __restrict__ B1, size_t sB,
    float* __restrict__ C,
    __nv_bfloat16* __restrict__ D0, __nv_bfloat16* __restrict__ D1,
    size_t sC, int ldc,
    int K, const float* __restrict__ bias, float alpha)
{
    __shared__ __align__(128) char smem[3 * 16384];
    const int bz = blockIdx.z;
    mma_body(A0 + (size_t)bz * sA, A1 + (size_t)bz * sA,
             B0 + (size_t)bz * sB, B1 + (size_t)bz * sB,
             C ? C + (size_t)bz * sC : nullptr,
             D0 ? D0 + (size_t)bz * sC : nullptr,
             D1 ? D1 + (size_t)bz * sC : nullptr,
             ldc, K, bias, alpha, smem_u32(smem));
}

// ======================= split / transpose-split (2-way) =======================
__global__ void split_kernel(const float* __restrict__ src,
                             __nv_bfloat16* __restrict__ d0,
                             __nv_bfloat16* __restrict__ d1, size_t n4)
{
    for (size_t i = (size_t)blockIdx.x * 256 + threadIdx.x; i < n4;
         i += (size_t)gridDim.x * 256) {
        float4 v = ((const float4*)src)[i];
        float vv[4] = { v.x, v.y, v.z, v.w };
        __nv_bfloat16 h0[4], h1[4];
        #pragma unroll
        for (int t = 0; t < 4; t++) {
            h0[t] = __float2bfloat16(vv[t]);
            h1[t] = __float2bfloat16(vv[t] - __bfloat162float(h0[t]));
        }
        ((__nv_bfloat162*)d0)[2*i]   = __nv_bfloat162(h0[0], h0[1]);
        ((__nv_bfloat162*)d0)[2*i+1] = __nv_bfloat162(h0[2], h0[3]);
        ((__nv_bfloat162*)d1)[2*i]   = __nv_bfloat162(h1[0], h1[1]);
        ((__nv_bfloat162*)d1)[2*i+1] = __nv_bfloat162(h1[2], h1[3]);
    }
}

__global__ void tsplit_kernel(const float* __restrict__ src, int ld, size_t sSrc,
                              const float* __restrict__ mask,
                              const float* __restrict__ norms, int thr_base,
                              __nv_bfloat16* __restrict__ d0,
                              __nv_bfloat16* __restrict__ d1)
{
    __shared__ float tile[32][33];
    int bz = blockIdx.z;
    src += (size_t)bz * sSrc;
    const float* mk = mask ? (mask + (size_t)bz * S_) : nullptr;
    const float* nm = norms ? (norms + (size_t)bz * NTILE) : nullptr;
    float thr = nm ? g_thr[thr_base + bz] : 0.f;
    __nv_bfloat16* p0 = d0 + (size_t)bz * E_ * S_;
    __nv_bfloat16* p1 = d1 + (size_t)bz * E_ * S_;
    int e0 = blockIdx.x * 32, s0 = blockIdx.y * 32;
    int tx = threadIdx.x & 31, ty = threadIdx.x >> 5;
    #pragma unroll
    for (int i = ty; i < 32; i += 8) {
        int ss = s0 + i, ee = e0 + tx;
        float v = src[(size_t)ss * ld + ee];
        if (mk) v *= mk[ss];
        if (nm) {
            float n = nm[(ss >> 1) * (E_ / 2) + (ee >> 1)];
            if (n < thr) v = 0.f;
        }
        tile[i][tx] = v;
    }
    __syncthreads();
    #pragma unroll
    for (int i = ty; i < 32; i += 8) {
        float v = tile[tx][i];
        __nv_bfloat16 h = __float2bfloat16(v);
        __nv_bfloat16 l = __float2bfloat16(v - __bfloat162float(h));
        p0[(size_t)(e0 + i) * S_ + s0 + tx] = h;
        p1[(size_t)(e0 + i) * S_ + s0 + tx] = l;
    }
}

// ======================= norms =======================
__global__ void tile_norms_kernel() {
    int idx = blockIdx.x * 256 + threadIdx.x;
    int which = idx / (B_ * NTILE);
    int rem   = idx % (B_ * NTILE);
    int b = rem / NTILE, t = rem % NTILE;
    int s2 = t / (E_ / 2), d2 = t % (E_ / 2);
    const float* p = g_qkv + (size_t)(b * S_ + 2 * s2) * QKV_LD + which * E_ + 2 * d2;
    float v00 = p[0], v01 = p[1], v10 = p[QKV_LD], v11 = p[QKV_LD + 1];
    float n = sqrtf(v00 * v00 + v01 * v01 + v10 * v10 + v11 * v11);
    (which ? g_norm_k : g_norm_q)[rem] = n;
}

__global__ void wo_norms_kernel(const float* __restrict__ WO) {
    __shared__ float sh[256];
    int row = blockIdx.x;
    const float* p = WO + (size_t)row * E_;
    float s = 0.f;
    for (int i = threadIdx.x; i < E_; i += 256) { float v = p[i]; s += v * v; }
    sh[threadIdx.x] = s; __syncthreads();
    for (int o = 128; o > 0; o >>= 1) {
        if (threadIdx.x < o) sh[threadIdx.x] += sh[threadIdx.x + o];
        __syncthreads();
    }
    if (threadIdx.x == 0) g_norm_wo[row] = sqrtf(sh[0]);
}

// ======================= q,k median via batched radix select (sels 0..7) =========
__global__ void sel_init_kernel() {
    int t = threadIdx.x;
    for (int s = 0; s < NSEL; s++) g_hist[s][t] = 0;
    if (t < 8) {
        g_prefix[t] = 0;
        g_kk[t] = NTILE / 2;
        g_cntless[t] = 0;
        g_maxbelow[t] = 0;
    }
}

__global__ void sel_hist_kernel(int round) {
    __shared__ unsigned sh[256];
    int sel = blockIdx.y;
    const float* p; int n; sel_info(sel, &p, &n);
    sh[threadIdx.x] = 0; __syncthreads();
    unsigned himask = (round == 0) ? 0u : (0xFFFFFFFFu << (32 - 8 * round));
    unsigned pref = g_prefix[sel];
    int shift = 24 - 8 * round;
    for (int i = blockIdx.x * 256 + threadIdx.x; i < n; i += gridDim.x * 256) {
        unsigned bits = __float_as_uint(p[i]);
        if ((bits & himask) == pref) atomicAdd(&sh[(bits >> shift) & 255], 1u);
    }
    __syncthreads();
    if (sh[threadIdx.x]) atomicAdd(&g_hist[sel][threadIdx.x], sh[threadIdx.x]);
}

__global__ void sel_scan_kernel(int round) {
    int sel = threadIdx.x;
    if (sel >= 8) return;
    int need = g_kk[sel];
    unsigned cum = 0; int bin = 255;
    for (int i = 0; i < 256; i++) {
        unsigned c = g_hist[sel][i];
        if (cum + c > (unsigned)need) { bin = i; break; }
        cum += c;
    }
    g_kk[sel] = need - (int)cum;
    g_prefix[sel] |= ((unsigned)bin) << (24 - 8 * round);
    for (int i = 0; i < 256; i++) g_hist[sel][i] = 0;
}

__global__ void sel_fin1_kernel() {
    __shared__ unsigned scnt, smax;
    int sel = blockIdx.y;
    const float* p; int n; sel_info(sel, &p, &n);
    if (threadIdx.x == 0) { scnt = 0; smax = 0; }
    __syncthreads();
    float bval = __uint_as_float(g_prefix[sel]);
    unsigned cnt = 0, mx = 0;
    for (int i = blockIdx.x * 256 + threadIdx.x; i < n; i += gridDim.x * 256) {
        float v = p[i];
        if (v < bval) { cnt++; unsigned bv = __float_as_uint(v); if (bv > mx) mx = bv; }
    }
    atomicAdd(&scnt, cnt); atomicMax(&smax, mx);
    __syncthreads();
    if (threadIdx.x == 0) {
        if (scnt) atomicAdd(&g_cntless[sel], scnt);
        atomicMax(&g_maxbelow[sel], smax);
    }
}

__global__ void sel_fin2_kernel() {
    int sel = threadIdx.x;
    if (sel >= 8) return;
    unsigned kt = (unsigned)(NTILE / 2);
    float b = __uint_as_float(g_prefix[sel]);
    float a = (g_cntless[sel] == kt) ? __uint_as_float(g_maxbelow[sel]) : b;
    g_thr[sel] = 0.5f * (a + b);
}

// ======================= WO median: one block per batch (same algorithm) =========
__global__ void wo_median_kernel() {
    __shared__ float vals[S_];
    __shared__ unsigned hist[256];
    __shared__ unsigned s_prefix, s_need, s_cnt, s_max;
    int b = blockIdx.x, tid = threadIdx.x;
    for (int i = tid; i < S_; i += 256) vals[i] = g_norm_wo[b * S_ + i];
    if (tid == 0) { s_prefix = 0; s_need = S_ / 2; }
    __syncthreads();
    for (int round = 0; round < 4; ++round) {
        hist[tid] = 0;
        __syncthreads();
        unsigned himask = (round == 0) ? 0u : (0xFFFFFFFFu << (32 - 8 * round));
        unsigned pref = s_prefix;
        int shift = 24 - 8 * round;
        for (int i = tid; i < S_; i += 256) {
            unsigned bits = __float_as_uint(vals[i]);
            if ((bits & himask) == pref) atomicAdd(&hist[(bits >> shift) & 255], 1u);
        }
        __syncthreads();
        if (tid == 0) {
            int need = (int)s_need;
            unsigned cum = 0; int bin = 255;
            for (int i = 0; i < 256; i++) {
                unsigned c = hist[i];
                if (cum + c > (unsigned)need) { bin = i; break; }
                cum += c;
            }
            s_need = (unsigned)(need - (int)cum);
            s_prefix = pref | ((unsigned)bin << shift);
        }
        __syncthreads();
    }
    if (tid == 0) { s_cnt = 0; s_max = 0; }
    __syncthreads();
    float bval = __uint_as_float(s_prefix);
    unsigned cnt = 0, mx = 0;
    for (int i = tid; i < S_; i += 256) {
        float v = vals[i];
        if (v < bval) { cnt++; unsigned bv = __float_as_uint(v); if (bv > mx) mx = bv; }
    }
    if (cnt) atomicAdd(&s_cnt, cnt);
    atomicMax(&s_max, mx);
    __syncthreads();
    if (tid == 0) {
        float a = (s_cnt == (unsigned)(S_ / 2)) ? __uint_as_float(s_max) : bval;
        g_thr[8 + b] = 0.5f * (a + bval);
    }
}

__global__ void wmask_kernel() {
    int i = blockIdx.x * 256 + threadIdx.x;
    if (i >= B_ * S_) return;
    int b = i / S_;
    g_wmask[i] = (g_norm_wo[i] >= g_thr[8 + b]) ? 1.f : 0.f;
}

// ======================= launch =======================
extern "C" void kernel_launch(void* const* d_in, const int* in_sizes, int n_in,
                              void* d_out, int out_size)
{
    const float* x    = (const float*)d_in[0];   // [4,2048,1024]
    const float* Wqkv = (const float*)d_in[1];   // [3072,1024]
    const float* bqkv = (const float*)d_in[2];   // [3072]
    const float* WO   = (const float*)d_in[3];   // [4,1,2048,1024]
    float* out        = (float*)d_out;           // [4,2048,1024]
    (void)in_sizes; (void)n_in; (void)out_size;

    float *qkv, *wmask, *nq, *nk;
    cudaGetSymbolAddress((void**)&qkv,   g_qkv);
    cudaGetSymbolAddress((void**)&wmask, g_wmask);
    cudaGetSymbolAddress((void**)&nq,    g_norm_q);
    cudaGetSymbolAddress((void**)&nk,    g_norm_k);
    __nv_bfloat16 *x0,*x1, *wv0,*wv1, *xT0,*xT1, *qT0,*qT1, *kT0,*kT1,
                  *vT0,*vT1, *oT0,*oT1, *am0,*am1, *h10,*h11, *gt0,*gt1,
                  *tt0,*tt1, *ut0,*ut1;
    cudaGetSymbolAddress((void**)&x0, g_x0); cudaGetSymbolAddress((void**)&x1, g_x1);
    cudaGetSymbolAddress((void**)&wv0, g_wv0); cudaGetSymbolAddress((void**)&wv1, g_wv1);
    cudaGetSymbolAddress((void**)&xT0, g_xT0); cudaGetSymbolAddress((void**)&xT1, g_xT1);
    cudaGetSymbolAddress((void**)&qT0, g_qT0); cudaGetSymbolAddress((void**)&qT1, g_qT1);
    cudaGetSymbolAddress((void**)&kT0, g_kT0); cudaGetSymbolAddress((void**)&kT1, g_kT1);
    cudaGetSymbolAddress((void**)&vT0, g_vT0); cudaGetSymbolAddress((void**)&vT1, g_vT1);
    cudaGetSymbolAddress((void**)&oT0, g_oT0); cudaGetSymbolAddress((void**)&oT1, g_oT1);
    cudaGetSymbolAddress((void**)&am0, g_am0); cudaGetSymbolAddress((void**)&am1, g_am1);
    cudaGetSymbolAddress((void**)&h10, g_h10); cudaGetSymbolAddress((void**)&h11, g_h11);
    cudaGetSymbolAddress((void**)&gt0, g_gt0); cudaGetSymbolAddress((void**)&gt1, g_gt1);
    cudaGetSymbolAddress((void**)&tt0, g_tt0); cudaGetSymbolAddress((void**)&tt1, g_tt1);
    cudaGetSymbolAddress((void**)&ut0, g_ut0); cudaGetSymbolAddress((void**)&ut1, g_ut1);

    const size_t EE = (size_t)E_ * E_;
    const size_t SE = (size_t)S_ * E_;
    const size_t ES = (size_t)E_ * S_;

    // fork/join resources: fresh per call, never destroyed (destroying a stream
    // during capture invalidates it; a few leaked host handles are harmless).
    cudaStream_t sB;
    cudaStreamCreateWithFlags(&sB, cudaStreamNonBlocking);
    cudaEvent_t evFork, evB;
    cudaEventCreateWithFlags(&evFork, cudaEventDisableTiming);
    cudaEventCreateWithFlags(&evB, cudaEventDisableTiming);

    // ---- common prefix on default stream ----
    split_kernel<<<2048, 256>>>(x, x0, x1, B_*SE/4);
    split_kernel<<<2048, 256>>>(Wqkv + 2048 * E_, wv0, wv1, EE/4);
    cudaEventRecord(evFork, 0);
    cudaStreamWaitEvent(sB, evFork, 0);

    // ---- stream B: tensor/memory-bound subgraph (independent of q,k) ----
    mma_nt<<<dim3(E_/128, (B_*S_)/128, 1), 256, 0, sB>>>(
        x0, x1, 0, wv0, wv1, 0, qkv + 2048, nullptr, nullptr, 0, QKV_LD,
        E_, bqkv + 2048, 1.f);                                   // v columns
    dim3 tg(E_/32, S_/32, B_);
    tsplit_kernel<<<tg, 256, 0, sB>>>(x, E_, SE, nullptr, nullptr, 0, xT0, xT1);
    wo_norms_kernel<<<B_ * S_, 256, 0, sB>>>(WO);
    wo_median_kernel<<<B_, 256, 0, sB>>>();
    wmask_kernel<<<(B_ * S_) / 256, 256, 0, sB>>>();
    tsplit_kernel<<<tg, 256, 0, sB>>>(WO, E_, SE, wmask, nullptr, 0, oT0, oT1);
    tsplit_kernel<<<tg, 256, 0, sB>>>(qkv + 2*E_, QKV_LD, (size_t)S_*QKV_LD,
                                      nullptr, nullptr, 0, vT0, vT1);
    dim3 ge(E_/128, E_/128, B_);
    mma_nt<<<ge, 256, 0, sB>>>(xT0, xT1, ES, vT0, vT1, ES,
                               nullptr, h10, h11, EE, E_, S_, nullptr, 1.f); // H1
    mma_nt<<<ge, 256, 0, sB>>>(xT0, xT1, ES, oT0, oT1, ES,
                               nullptr, gt0, gt1, EE, E_, S_, nullptr, 1.f); // Gt
    mma_nt<<<ge, 256, 0, sB>>>(gt0, gt1, EE, h10, h11, EE,
                               nullptr, tt0, tt1, EE, E_, E_, nullptr, 1.f); // Tt
    cudaEventRecord(evB, sB);

    // ---- stream A (default): fp32 mask-critical path ----
    sgemm_nt<<<dim3(2048 / BN, (B_ * S_) / BM, 1), 256>>>(
        x, E_, Wqkv, E_, qkv, QKV_LD, B_ * S_, 2048, E_, bqkv);  // q,k columns
    tile_norms_kernel<<<(2 * B_ * NTILE) / 256, 256>>>();
    sel_init_kernel<<<1, 256>>>();
    for (int r = 0; r < 4; r++) {
        sel_hist_kernel<<<dim3(64, 8), 256>>>(r);
        sel_scan_kernel<<<1, 32>>>(r);
    }
    sel_fin1_kernel<<<dim3(64, 8), 256>>>();
    sel_fin2_kernel<<<1, 32>>>();
    tsplit_kernel<<<tg, 256>>>(qkv + 0,  QKV_LD, (size_t)S_*QKV_LD, nullptr, nq, 0, qT0, qT1);
    tsplit_kernel<<<tg, 256>>>(qkv + E_, QKV_LD, (size_t)S_*QKV_LD, nullptr, nk, 4, kT0, kT1);
    mma_nt<<<ge, 256>>>(qT0, qT1, ES, kT0, kT1, ES,
                        nullptr, am0, am1, EE, E_, S_, nullptr, 1.f);        // Am

    // ---- join: Ut needs Tt (B) + Am (A); out needs Ut ----
    cudaStreamWaitEvent(0, evB, 0);
    mma_nt<<<ge, 256>>>(tt0, tt1, EE, am0, am1, EE,
                        nullptr, ut0, ut1, EE, E_, E_, nullptr, 1.f / 32.f); // Ut
    mma_nt<<<dim3(E_/128, S_/128, B_), 256>>>(
        x0, x1, SE, ut0, ut1, EE,
        out, nullptr, nullptr, SE, E_, E_, nullptr, 1.f);                    // out
}

// round 16
// speedup vs baseline: 2.0183x; 1.0111x over previous
#include <cuda_runtime.h>
#include <cuda_bf16.h>
#include <stdint.h>

#define B_    4
#define S_    2048
#define E_    1024
#define QKV_LD 3072
#define NTILE ((S_/2)*(E_/2))   // 524288 tiles per (b, q|k)
#define NSEL  12                // storage; batched radix uses 0..7 (q,k)

// ======================= PTX helpers =======================
__device__ __forceinline__ uint32_t smem_u32(const void* p) {
    uint32_t a;
    asm("{ .reg .u64 t; cvta.to.shared.u64 t, %1; cvt.u32.u64 %0, t; }" : "=r"(a) : "l"(p));
    return a;
}
#define CP_ASYNC16(s, g) \
    asm volatile("cp.async.cg.shared.global [%0], [%1], 16;" :: "r"(s), "l"(g))
#define CP_COMMIT() asm volatile("cp.async.commit_group;" ::: "memory")
#define CP_WAIT1()  asm volatile("cp.async.wait_group 1;" ::: "memory")
#define CP_WAIT0()  asm volatile("cp.async.wait_group 0;" ::: "memory")
#define LDSM4(r0, r1, r2, r3, a) \
    asm volatile("ldmatrix.sync.aligned.m8n8.x4.shared.b16 {%0,%1,%2,%3}, [%4];" \
        : "=r"(r0), "=r"(r1), "=r"(r2), "=r"(r3) : "r"(a))
#define MMA16816(c, a, b) \
    asm volatile("mma.sync.aligned.m16n8k16.row.col.f32.bf16.bf16.f32 " \
        "{%0,%1,%2,%3}, {%4,%5,%6,%7}, {%8,%9}, {%0,%1,%2,%3};" \
        : "+f"((c)[0]), "+f"((c)[1]), "+f"((c)[2]), "+f"((c)[3]) \
        : "r"((a)[0]), "r"((a)[1]), "r"((a)[2]), "r"((a)[3]), "r"((b)[0]), "r"((b)[1]))

// 8x8-matrix-blocked smem layout for a 128x16 bf16 tile (4 KB)
__device__ __forceinline__ uint32_t tile_off(int row, int ks) {
    return (uint32_t)((((row >> 3) * 2 + ks) * 128) + ((((row & 7) ^ (ks * 2)) & 7) * 16));
}

// ======================= scratch (device globals) =======================
__device__ float g_qkv[B_*S_*QKV_LD];          // [b, s, 3E] fp32
__device__ float g_norm_q[B_*NTILE];
__device__ float g_norm_k[B_*NTILE];
__device__ float g_norm_wo[B_*S_];
__device__ float g_wmask[B_*S_];

// bf16 hi/lo splits
__device__ __nv_bfloat16 g_x0[B_*S_*E_],  g_x1[B_*S_*E_];
__device__ __nv_bfloat16 g_wv0[E_*E_],    g_wv1[E_*E_];    // v rows of Wqkv
__device__ __nv_bfloat16 g_xT0[B_*E_*S_], g_xT1[B_*E_*S_];
__device__ __nv_bfloat16 g_qT0[B_*E_*S_], g_qT1[B_*E_*S_];
__device__ __nv_bfloat16 g_kT0[B_*E_*S_], g_kT1[B_*E_*S_];
__device__ __nv_bfloat16 g_vT0[B_*E_*S_], g_vT1[B_*E_*S_];
__device__ __nv_bfloat16 g_oT0[B_*E_*S_], g_oT1[B_*E_*S_];
__device__ __nv_bfloat16 g_am0[B_*E_*E_], g_am1[B_*E_*E_];
__device__ __nv_bfloat16 g_h10[B_*E_*E_], g_h11[B_*E_*E_];
__device__ __nv_bfloat16 g_gt0[B_*E_*E_], g_gt1[B_*E_*E_];
__device__ __nv_bfloat16 g_tt0[B_*E_*E_], g_tt1[B_*E_*E_];
__device__ __nv_bfloat16 g_ut0[B_*E_*E_], g_ut1[B_*E_*E_];

__device__ unsigned g_hist[NSEL][256];
__device__ unsigned g_prefix[NSEL];
__device__ int      g_kk[NSEL];
__device__ unsigned g_cntless[NSEL];
__device__ unsigned g_maxbelow[NSEL];
__device__ float    g_thr[NSEL];

__device__ __forceinline__ void sel_info(int sel, const float** p, int* n) {
    if (sel < 4) { *p = g_norm_q + (size_t)sel * NTILE;       *n = NTILE; }
    else         { *p = g_norm_k + (size_t)(sel-4) * NTILE;   *n = NTILE; }
}

// ======================= fp32 SGEMM (R2 arithmetic, NT) + fused tile norms ========
// Mainloop bit-identical to all passing kernels. Epilogue additionally computes
// the 2x2-tile norms directly from the post-bias register values (the exact
// floats being stored) and writes them to g_norm_q / g_norm_k.
#define BM 128
#define BN 128
#define BKK 16

__global__ void __launch_bounds__(256, 1) sgemm_nt(
    const float* __restrict__ A, int lda,
    const float* __restrict__ B, int ldb,
    float* __restrict__ C, int ldc,
    int M, int N, int K,
    const float* __restrict__ bias,
    float* __restrict__ nq, float* __restrict__ nk)
{
    __shared__ float As[BKK][BM];
    __shared__ float Bs[BKK][BN];
    const int bm = blockIdx.y * BM, bn = blockIdx.x * BN;
    const int tid = threadIdx.x;
    const int tx = tid & 15, ty = tid >> 4;

    float s[8][8];
    #pragma unroll
    for (int i = 0; i < 8; i++)
        #pragma unroll
        for (int j = 0; j < 8; j++) s[i][j] = 0.f;

    for (int k0 = 0; k0 < K; k0 += BKK) {
        #pragma unroll
        for (int i = 0; i < 2; i++) {
            int f = tid + i * 256;
            int r = f >> 2, c4 = f & 3;
            float4 v = *(const float4*)(A + (size_t)(bm + r) * lda + k0 + c4 * 4);
            As[c4 * 4 + 0][r] = v.x; As[c4 * 4 + 1][r] = v.y;
            As[c4 * 4 + 2][r] = v.z; As[c4 * 4 + 3][r] = v.w;
        }
        #pragma unroll
        for (int i = 0; i < 2; i++) {
            int f = tid + i * 256;
            int r = f >> 2, c4 = f & 3;
            float4 v = *(const float4*)(B + (size_t)(bn + r) * ldb + k0 + c4 * 4);
            Bs[c4 * 4 + 0][r] = v.x; Bs[c4 * 4 + 1][r] = v.y;
            Bs[c4 * 4 + 2][r] = v.z; Bs[c4 * 4 + 3][r] = v.w;
        }
        __syncthreads();

        float t[8][8];
        #pragma unroll
        for (int i = 0; i < 8; i++)
            #pragma unroll
            for (int j = 0; j < 8; j++) t[i][j] = 0.f;

        #pragma unroll
        for (int kk = 0; kk < BKK; kk++) {
            float a[8], b[8];
            *(float4*)&a[0] = *(float4*)&As[kk][ty * 8];
            *(float4*)&a[4] = *(float4*)&As[kk][ty * 8 + 4];
            *(float4*)&b[0] = *(float4*)&Bs[kk][tx * 8];
            *(float4*)&b[4] = *(float4*)&Bs[kk][tx * 8 + 4];
            #pragma unroll
            for (int i = 0; i < 8; i++)
                #pragma unroll
                for (int j = 0; j < 8; j++)
                    t[i][j] += a[i] * b[j];
        }
        #pragma unroll
        for (int i = 0; i < 8; i++)
            #pragma unroll
            for (int j = 0; j < 8; j++) s[i][j] += t[i][j];
        __syncthreads();
    }
    // epilogue: store post-bias values (identical arithmetic) and keep them in s
    #pragma unroll
    for (int i = 0; i < 8; i++) {
        int r = bm + ty * 8 + i;
        #pragma unroll
        for (int j = 0; j < 8; j += 4) {
            int c = bn + tx * 8 + j;
            float4 v = make_float4(s[i][j] * 1.f, s[i][j+1] * 1.f,
                                   s[i][j+2] * 1.f, s[i][j+3] * 1.f);
            if (bias) { v.x += bias[c]; v.y += bias[c+1]; v.z += bias[c+2]; v.w += bias[c+3]; }
            *(float4*)(C + (size_t)r * ldc + c) = v;
            s[i][j] = v.x; s[i][j+1] = v.y; s[i][j+2] = v.z; s[i][j+3] = v.w;
        }
    }
    // fused 2x2 tile norms (q cols 0-1023, k cols 1024-2047); same mul+fma chain
    // as the former tile_norms kernel.
    if (nq) {
        int which = (bn >= 1024);
        float* dst = which ? nk : nq;
        int r0 = bm + ty * 8;
        int b  = r0 >> 11;            // /S_
        int s0 = r0 & (S_ - 1);
        int ebase = (bn - which * 1024) + tx * 8;
        #pragma unroll
        for (int i = 0; i < 8; i += 2) {
            float4 nv;
            float* pn = &nv.x;
            #pragma unroll
            for (int j = 0; j < 8; j += 2) {
                float v00 = s[i][j],   v01 = s[i][j+1];
                float v10 = s[i+1][j], v11 = s[i+1][j+1];
                pn[j >> 1] = sqrtf(__fmaf_rn(v11, v11,
                                   __fmaf_rn(v10, v10,
                                   __fmaf_rn(v01, v01, v00 * v00))));
            }
            size_t idx = (size_t)b * NTILE
                       + (size_t)((s0 + i) >> 1) * (E_ / 2) + (ebase >> 1);
            *(float4*)(dst + idx) = nv;
        }
    }
}

// ======================= warp-MMA NT GEMM body (bf16x3, fp32 accum) =================
__device__ __forceinline__ void mma_body(
    const __nv_bfloat16* __restrict__ Apl0, const __nv_bfloat16* __restrict__ Apl1,
    const __nv_bfloat16* __restrict__ Bpl0, const __nv_bfloat16* __restrict__ Bpl1,
    float* __restrict__ Cp,
    __nv_bfloat16* __restrict__ d0, __nv_bfloat16* __restrict__ d1,
    int ldc, int K, const float* __restrict__ bias, float alpha, uint32_t sbase)
{
    const int tid = threadIdx.x;
    const int wid = tid >> 5, lane = tid & 31;
    const int bm = blockIdx.y * 128, bn = blockIdx.x * 128;
    const int nch = K >> 4;

    const int lr0 = tid >> 1, lks0 = tid & 1;
    const uint32_t so0 = tile_off(lr0, lks0);

    const int j01 = (lane >> 3) & 1;
    const int j23 = lane >> 4;
    const int lr  = lane & 7;
    const int wm = (wid & 3) * 32;
    const int wn = (wid >> 2) * 64;
    uint32_t aoff[2], boff[4];
    #pragma unroll
    for (int mf = 0; mf < 2; ++mf)
        aoff[mf] = tile_off(wm + mf * 16 + j01 * 8 + lr, j23);
    #pragma unroll
    for (int nf2 = 0; nf2 < 4; ++nf2)
        boff[nf2] = tile_off(wn + nf2 * 16 + j23 * 8 + lr, j01);

    float acc[2][8][4];
    #pragma unroll
    for (int mf = 0; mf < 2; ++mf)
        #pragma unroll
        for (int nf = 0; nf < 8; ++nf)
            #pragma unroll
            for (int q = 0; q < 4; ++q) acc[mf][nf][q] = 0.f;

    #pragma unroll 1
    for (int pc = 0; pc < 2; ++pc) {
        uint32_t base = sbase + (uint32_t)pc * 16384u;
        int k0 = pc << 4;
        size_t gA = (size_t)(bm + lr0) * K + k0 + lks0 * 8;
        size_t gB = (size_t)(bn + lr0) * K + k0 + lks0 * 8;
        CP_ASYNC16(base + so0,         Apl0 + gA);
        CP_ASYNC16(base + 4096 + so0,  Apl1 + gA);
        CP_ASYNC16(base + 8192 + so0,  Bpl0 + gB);
        CP_ASYNC16(base + 12288 + so0, Bpl1 + gB);
        CP_COMMIT();
    }

    int buf = 0, ibuf = 2;
    for (int c = 0; c < nch; ++c) {
        if (c + 1 < nch) { CP_WAIT1(); } else { CP_WAIT0(); }
        __syncthreads();
        const uint32_t base = sbase + (uint32_t)buf * 16384u;
        uint32_t af[2][2][4];
        #pragma unroll
        for (int mf = 0; mf < 2; ++mf) {
            LDSM4(af[0][mf][0], af[0][mf][1], af[0][mf][2], af[0][mf][3],
                  base + aoff[mf]);
            LDSM4(af[1][mf][0], af[1][mf][1], af[1][mf][2], af[1][mf][3],
                  base + 4096 + aoff[mf]);
        }
        {
            uint32_t bf[8][2];
            #pragma unroll
            for (int nf2 = 0; nf2 < 4; ++nf2) {
                uint32_t r0, r1, r2, r3;
                LDSM4(r0, r1, r2, r3, base + 8192 + boff[nf2]);
                bf[nf2*2][0] = r0;   bf[nf2*2][1] = r1;
                bf[nf2*2+1][0] = r2; bf[nf2*2+1][1] = r3;
            }
            #pragma unroll
            for (int mf = 0; mf < 2; ++mf)
                #pragma unroll
                for (int nf = 0; nf < 8; ++nf) {
                    MMA16816(acc[mf][nf], af[0][mf], bf[nf]);
                    MMA16816(acc[mf][nf], af[1][mf], bf[nf]);
                }
        }
        {
            uint32_t bf[8][2];
            #pragma unroll
            for (int nf2 = 0; nf2 < 4; ++nf2) {
                uint32_t r0, r1, r2, r3;
                LDSM4(r0, r1, r2, r3, base + 12288 + boff[nf2]);
                bf[nf2*2][0] = r0;   bf[nf2*2][1] = r1;
                bf[nf2*2+1][0] = r2; bf[nf2*2+1][1] = r3;
            }
            #pragma unroll
            for (int mf = 0; mf < 2; ++mf)
                #pragma unroll
                for (int nf = 0; nf < 8; ++nf)
                    MMA16816(acc[mf][nf], af[0][mf], bf[nf]);
        }
        if (c + 2 < nch) {
            uint32_t b2 = sbase + (uint32_t)ibuf * 16384u;
            int k0 = (c + 2) << 4;
            size_t gA = (size_t)(bm + lr0) * K + k0 + lks0 * 8;
            size_t gB = (size_t)(bn + lr0) * K + k0 + lks0 * 8;
            CP_ASYNC16(b2 + so0,         Apl0 + gA);
            CP_ASYNC16(b2 + 4096 + so0,  Apl1 + gA);
            CP_ASYNC16(b2 + 8192 + so0,  Bpl0 + gB);
            CP_ASYNC16(b2 + 12288 + so0, Bpl1 + gB);
            CP_COMMIT();
        }
        buf  = (buf  == 2) ? 0 : buf  + 1;
        ibuf = (ibuf == 2) ? 0 : ibuf + 1;
    }

    const int er = lane >> 2, ec = (lane & 3) * 2;
    if (d0) {
        #pragma unroll
        for (int mf = 0; mf < 2; ++mf)
            #pragma unroll
            for (int nf = 0; nf < 8; ++nf) {
                int row = bm + wm + mf * 16 + er;
                int col = bn + wn + nf * 8 + ec;
                #pragma unroll
                for (int h = 0; h < 2; ++h) {
                    float vx = acc[mf][nf][h*2]   * alpha;
                    float vy = acc[mf][nf][h*2+1] * alpha;
                    __nv_bfloat16 hx = __float2bfloat16(vx);
                    __nv_bfloat16 hy = __float2bfloat16(vy);
                    __nv_bfloat16 lx = __float2bfloat16(vx - __bfloat162float(hx));
                    __nv_bfloat16 ly = __float2bfloat16(vy - __bfloat162float(hy));
                    size_t o = (size_t)(row + h * 8) * ldc + col;
                    *(__nv_bfloat162*)(d0 + o) = __nv_bfloat162(hx, hy);
                    *(__nv_bfloat162*)(d1 + o) = __nv_bfloat162(lx, ly);
                }
            }
    } else {
        #pragma unroll
        for (int mf = 0; mf < 2; ++mf)
            #pragma unroll
            for (int nf = 0; nf < 8; ++nf) {
                int row = bm + wm + mf * 16 + er;
                int col = bn + wn + nf * 8 + ec;
                float bx = 0.f, by = 0.f;
                if (bias) { bx = bias[col]; by = bias[col + 1]; }
                float2 v0 = { acc[mf][nf][0] * alpha + bx, acc[mf][nf][1] * alpha + by };
                float2 v1 = { acc[mf][nf][2] * alpha + bx, acc[mf][nf][3] * alpha + by };
                *(float2*)(Cp + (size_t)row * ldc + col) = v0;
                *(float2*)(Cp + (size_t)(row + 8) * ldc + col) = v1;
            }
    }
}

__global__ void __launch_bounds__(256, 2) mma_nt(
    const __nv_bfloat16* __restrict__ A0, const __nv_bfloat16* __restrict__ A1, size_t sA,
    const __nv_bfloat16* __restrict__ B0, const __nv_bfloat16* __restrict__ B1, size_t sB,
    float* __restrict__ C,
    __nv_bfloat16* __restrict__ D0, __nv_bfloat16* __restrict__ D1,
    size_t sC, int ldc,
    int K, const float* __restrict__ bias, float alpha)
{
    __shared__ __align__(128) char smem[3 * 16384];
    const int bz = blockIdx.z;
    mma_body(A0 + (size_t)bz * sA, A1 + (size_t)bz * sA,
             B0 + (size_t)bz * sB, B1 + (size_t)bz * sB,
             C ? C + (size_t)bz * sC : nullptr,
             D0 ? D0 + (size_t)bz * sC : nullptr,
             D1 ? D1 + (size_t)bz * sC : nullptr,
             ldc, K, bias, alpha, smem_u32(smem));
}

// ======================= split / transpose-split (2-way) =======================
__global__ void split_kernel(const float* __restrict__ src,
                             __nv_bfloat16* __restrict__ d0,
                             __nv_bfloat16* __restrict__ d1, size_t n4)
{
    for (size_t i = (size_t)blockIdx.x * 256 + threadIdx.x; i < n4;
         i += (size_t)gridDim.x * 256) {
        float4 v = ((const float4*)src)[i];
        float vv[4] = { v.x, v.y, v.z, v.w };
        __nv_bfloat16 h0[4], h1[4];
        #pragma unroll
        for (int t = 0; t < 4; t++) {
            h0[t] = __float2bfloat16(vv[t]);
            h1[t] = __float2bfloat16(vv[t] - __bfloat162float(h0[t]));
        }
        ((__nv_bfloat162*)d0)[2*i]   = __nv_bfloat162(h0[0], h0[1]);
        ((__nv_bfloat162*)d0)[2*i+1] = __nv_bfloat162(h0[2], h0[3]);
        ((__nv_bfloat162*)d1)[2*i]   = __nv_bfloat162(h1[0], h1[1]);
        ((__nv_bfloat162*)d1)[2*i+1] = __nv_bfloat162(h1[2], h1[3]);
    }
}

__global__ void tsplit_kernel(const float* __restrict__ src, int ld, size_t sSrc,
                              const float* __restrict__ mask,
                              const float* __restrict__ norms, int thr_base,
                              __nv_bfloat16* __restrict__ d0,
                              __nv_bfloat16* __restrict__ d1)
{
    __shared__ float tile[32][33];
    int bz = blockIdx.z;
    src += (size_t)bz * sSrc;
    const float* mk = mask ? (mask + (size_t)bz * S_) : nullptr;
    const float* nm = norms ? (norms + (size_t)bz * NTILE) : nullptr;
    float thr = nm ? g_thr[thr_base + bz] : 0.f;
    __nv_bfloat16* p0 = d0 + (size_t)bz * E_ * S_;
    __nv_bfloat16* p1 = d1 + (size_t)bz * E_ * S_;
    int e0 = blockIdx.x * 32, s0 = blockIdx.y * 32;
    int tx = threadIdx.x & 31, ty = threadIdx.x >> 5;
    #pragma unroll
    for (int i = ty; i < 32; i += 8) {
        int ss = s0 + i, ee = e0 + tx;
        float v = src[(size_t)ss * ld + ee];
        if (mk) v *= mk[ss];
        if (nm) {
            float n = nm[(ss >> 1) * (E_ / 2) + (ee >> 1)];
            if (n < thr) v = 0.f;
        }
        tile[i][tx] = v;
    }
    __syncthreads();
    #pragma unroll
    for (int i = ty; i < 32; i += 8) {
        float v = tile[tx][i];
        __nv_bfloat16 h = __float2bfloat16(v);
        __nv_bfloat16 l = __float2bfloat16(v - __bfloat162float(h));
        p0[(size_t)(e0 + i) * S_ + s0 + tx] = h;
        p1[(size_t)(e0 + i) * S_ + s0 + tx] = l;
    }
}

// ======================= norms (WO only; q,k fused into sgemm) =======================
__global__ void wo_norms_kernel(const float* __restrict__ WO) {
    __shared__ float sh[256];
    int row = blockIdx.x;
    const float* p = WO + (size_t)row * E_;
    float s = 0.f;
    for (int i = threadIdx.x; i < E_; i += 256) { float v = p[i]; s += v * v; }
    sh[threadIdx.x] = s; __syncthreads();
    for (int o = 128; o > 0; o >>= 1) {
        if (threadIdx.x < o) sh[threadIdx.x] += sh[threadIdx.x + o];
        __syncthreads();
    }
    if (threadIdx.x == 0) g_norm_wo[row] = sqrtf(sh[0]);
}

// ======================= q,k median via batched radix select (sels 0..7) =========
__global__ void sel_init_kernel() {
    int t = threadIdx.x;
    for (int s = 0; s < NSEL; s++) g_hist[s][t] = 0;
    if (t < 8) {
        g_prefix[t] = 0;
        g_kk[t] = NTILE / 2;
        g_cntless[t] = 0;
        g_maxbelow[t] = 0;
    }
}

__global__ void sel_hist_kernel(int round) {
    __shared__ unsigned sh[256];
    int sel = blockIdx.y;
    const float* p; int n; sel_info(sel, &p, &n);
    sh[threadIdx.x] = 0; __syncthreads();
    unsigned himask = (round == 0) ? 0u : (0xFFFFFFFFu << (32 - 8 * round));
    unsigned pref = g_prefix[sel];
    int shift = 24 - 8 * round;
    for (int i = blockIdx.x * 256 + threadIdx.x; i < n; i += gridDim.x * 256) {
        unsigned bits = __float_as_uint(p[i]);
        if ((bits & himask) == pref) atomicAdd(&sh[(bits >> shift) & 255], 1u);
    }
    __syncthreads();
    if (sh[threadIdx.x]) atomicAdd(&g_hist[sel][threadIdx.x], sh[threadIdx.x]);
}

__global__ void sel_scan_kernel(int round) {
    int sel = threadIdx.x;
    if (sel >= 8) return;
    int need = g_kk[sel];
    unsigned cum = 0; int bin = 255;
    for (int i = 0; i < 256; i++) {
        unsigned c = g_hist[sel][i];
        if (cum + c > (unsigned)need) { bin = i; break; }
        cum += c;
    }
    g_kk[sel] = need - (int)cum;
    g_prefix[sel] |= ((unsigned)bin) << (24 - 8 * round);
    for (int i = 0; i < 256; i++) g_hist[sel][i] = 0;
}

__global__ void sel_fin1_kernel() {
    __shared__ unsigned scnt, smax;
    int sel = blockIdx.y;
    const float* p; int n; sel_info(sel, &p, &n);
    if (threadIdx.x == 0) { scnt = 0; smax = 0; }
    __syncthreads();
    float bval = __uint_as_float(g_prefix[sel]);
    unsigned cnt = 0, mx = 0;
    for (int i = blockIdx.x * 256 + threadIdx.x; i < n; i += gridDim.x * 256) {
        float v = p[i];
        if (v < bval) { cnt++; unsigned bv = __float_as_uint(v); if (bv > mx) mx = bv; }
    }
    atomicAdd(&scnt, cnt); atomicMax(&smax, mx);
    __syncthreads();
    if (threadIdx.x == 0) {
        if (scnt) atomicAdd(&g_cntless[sel], scnt);
        atomicMax(&g_maxbelow[sel], smax);
    }
}

__global__ void sel_fin2_kernel() {
    int sel = threadIdx.x;
    if (sel >= 8) return;
    unsigned kt = (unsigned)(NTILE / 2);
    float b = __uint_as_float(g_prefix[sel]);
    float a = (g_cntless[sel] == kt) ? __uint_as_float(g_maxbelow[sel]) : b;
    g_thr[sel] = 0.5f * (a + b);
}

// ======================= WO median: one block per batch =========
__global__ void wo_median_kernel() {
    __shared__ float vals[S_];
    __shared__ unsigned hist[256];
    __shared__ unsigned s_prefix, s_need, s_cnt, s_max;
    int b = blockIdx.x, tid = threadIdx.x;
    for (int i = tid; i < S_; i += 256) vals[i] = g_norm_wo[b * S_ + i];
    if (tid == 0) { s_prefix = 0; s_need = S_ / 2; }
    __syncthreads();
    for (int round = 0; round < 4; ++round) {
        hist[tid] = 0;
        __syncthreads();
        unsigned himask = (round == 0) ? 0u : (0xFFFFFFFFu << (32 - 8 * round));
        unsigned pref = s_prefix;
        int shift = 24 - 8 * round;
        for (int i = tid; i < S_; i += 256) {
            unsigned bits = __float_as_uint(vals[i]);
            if ((bits & himask) == pref) atomicAdd(&hist[(bits >> shift) & 255], 1u);
        }
        __syncthreads();
        if (tid == 0) {
            int need = (int)s_need;
            unsigned cum = 0; int bin = 255;
            for (int i = 0; i < 256; i++) {
                unsigned c = hist[i];
                if (cum + c > (unsigned)need) { bin = i; break; }
                cum += c;
            }
            s_need = (unsigned)(need - (int)cum);
            s_prefix = pref | ((unsigned)bin << shift);
        }
        __syncthreads();
    }
    if (tid == 0) { s_cnt = 0; s_max = 0; }
    __syncthreads();
    float bval = __uint_as_float(s_prefix);
    unsigned cnt = 0, mx = 0;
    for (int i = tid; i < S_; i += 256) {
        float v = vals[i];
        if (v < bval) { cnt++; unsigned bv = __float_as_uint(v); if (bv > mx) mx = bv; }
    }
    if (cnt) atomicAdd(&s_cnt, cnt);
    atomicMax(&s_max, mx);
    __syncthreads();
    if (tid == 0) {
        float a = (s_cnt == (unsigned)(S_ / 2)) ? __uint_as_float(s_max) : bval;
        g_thr[8 + b] = 0.5f * (a + bval);
    }
}

__global__ void wmask_kernel() {
    int i = blockIdx.x * 256 + threadIdx.x;
    if (i >= B_ * S_) return;
    int b = i / S_;
    g_wmask[i] = (g_norm_wo[i] >= g_thr[8 + b]) ? 1.f : 0.f;
}

// ======================= launch =======================
extern "C" void kernel_launch(void* const* d_in, const int* in_sizes, int n_in,
                              void* d_out, int out_size)
{
    const float* x    = (const float*)d_in[0];   // [4,2048,1024]
    const float* Wqkv = (const float*)d_in[1];   // [3072,1024]
    const float* bqkv = (const float*)d_in[2];   // [3072]
    const float* WO   = (const float*)d_in[3];   // [4,1,2048,1024]
    float* out        = (float*)d_out;           // [4,2048,1024]
    (void)in_sizes; (void)n_in; (void)out_size;

    float *qkv, *wmask, *nq, *nk;
    cudaGetSymbolAddress((void**)&qkv,   g_qkv);
    cudaGetSymbolAddress((void**)&wmask, g_wmask);
    cudaGetSymbolAddress((void**)&nq,    g_norm_q);
    cudaGetSymbolAddress((void**)&nk,    g_norm_k);
    __nv_bfloat16 *x0,*x1, *wv0,*wv1, *xT0,*xT1, *qT0,*qT1, *kT0,*kT1,
                  *vT0,*vT1, *oT0,*oT1, *am0,*am1, *h10,*h11, *gt0,*gt1,
                  *tt0,*tt1, *ut0,*ut1;
    cudaGetSymbolAddress((void**)&x0, g_x0); cudaGetSymbolAddress((void**)&x1, g_x1);
    cudaGetSymbolAddress((void**)&wv0, g_wv0); cudaGetSymbolAddress((void**)&wv1, g_wv1);
    cudaGetSymbolAddress((void**)&xT0, g_xT0); cudaGetSymbolAddress((void**)&xT1, g_xT1);
    cudaGetSymbolAddress((void**)&qT0, g_qT0); cudaGetSymbolAddress((void**)&qT1, g_qT1);
    cudaGetSymbolAddress((void**)&kT0, g_kT0); cudaGetSymbolAddress((void**)&kT1, g_kT1);
    cudaGetSymbolAddress((void**)&vT0, g_vT0); cudaGetSymbolAddress((void**)&vT1, g_vT1);
    cudaGetSymbolAddress((void**)&oT0, g_oT0); cudaGetSymbolAddress((void**)&oT1, g_oT1);
    cudaGetSymbolAddress((void**)&am0, g_am0); cudaGetSymbolAddress((void**)&am1, g_am1);
    cudaGetSymbolAddress((void**)&h10, g_h10); cudaGetSymbolAddress((void**)&h11, g_h11);
    cudaGetSymbolAddress((void**)&gt0, g_gt0); cudaGetSymbolAddress((void**)&gt1, g_gt1);
    cudaGetSymbolAddress((void**)&tt0, g_tt0); cudaGetSymbolAddress((void**)&tt1, g_tt1);
    cudaGetSymbolAddress((void**)&ut0, g_ut0); cudaGetSymbolAddress((void**)&ut1, g_ut1);

    const size_t EE = (size_t)E_ * E_;
    const size_t SE = (size_t)S_ * E_;
    const size_t ES = (size_t)E_ * S_;

    // fork/join resources: fresh per call, never destroyed (R14-proven clean;
    // plain nonblocking streams only — priority streams leak 2MB device mem).
    cudaStream_t sB;
    cudaStreamCreateWithFlags(&sB, cudaStreamNonBlocking);
    cudaEvent_t evFork, evB;
    cudaEventCreateWithFlags(&evFork, cudaEventDisableTiming);
    cudaEventCreateWithFlags(&evB, cudaEventDisableTiming);

    // ---- common prefix on default stream ----
    split_kernel<<<2048, 256>>>(x, x0, x1, B_*SE/4);
    split_kernel<<<2048, 256>>>(Wqkv + 2048 * E_, wv0, wv1, EE/4);
    sel_init_kernel<<<1, 256>>>();
    cudaEventRecord(evFork, 0);
    cudaStreamWaitEvent(sB, evFork, 0);

    // ---- stream B: tensor/memory-bound subgraph (independent of q,k) ----
    mma_nt<<<dim3(E_/128, (B_*S_)/128, 1), 256, 0, sB>>>(
        x0, x1, 0, wv0, wv1, 0, qkv + 2048, nullptr, nullptr, 0, QKV_LD,
        E_, bqkv + 2048, 1.f);                                   // v columns
    dim3 tg(E_/32, S_/32, B_);
    tsplit_kernel<<<tg, 256, 0, sB>>>(x, E_, SE, nullptr, nullptr, 0, xT0, xT1);
    wo_norms_kernel<<<B_ * S_, 256, 0, sB>>>(WO);
    wo_median_kernel<<<B_, 256, 0, sB>>>();
    wmask_kernel<<<(B_ * S_) / 256, 256, 0, sB>>>();
    tsplit_kernel<<<tg, 256, 0, sB>>>(WO, E_, SE, wmask, nullptr, 0, oT0, oT1);
    tsplit_kernel<<<tg, 256, 0, sB>>>(qkv + 2*E_, QKV_LD, (size_t)S_*QKV_LD,
                                      nullptr, nullptr, 0, vT0, vT1);
    dim3 ge(E_/128, E_/128, B_);
    mma_nt<<<ge, 256, 0, sB>>>(xT0, xT1, ES, vT0, vT1, ES,
                               nullptr, h10, h11, EE, E_, S_, nullptr, 1.f); // H1
    mma_nt<<<ge, 256, 0, sB>>>(xT0, xT1, ES, oT0, oT1, ES,
                               nullptr, gt0, gt1, EE, E_, S_, nullptr, 1.f); // Gt
    mma_nt<<<ge, 256, 0, sB>>>(gt0, gt1, EE, h10, h11, EE,
                               nullptr, tt0, tt1, EE, E_, E_, nullptr, 1.f); // Tt
    cudaEventRecord(evB, sB);

    // ---- stream 0: fp32 mask-critical path (norms fused into sgemm epilogue) ----
    sgemm_nt<<<dim3(2048 / BN, (B_ * S_) / BM, 1), 256>>>(
        x, E_, Wqkv, E_, qkv, QKV_LD, B_ * S_, 2048, E_, bqkv, nq, nk);
    for (int r = 0; r < 4; r++) {
        sel_hist_kernel<<<dim3(64, 8), 256>>>(r);
        sel_scan_kernel<<<1, 32>>>(r);
    }
    sel_fin1_kernel<<<dim3(64, 8), 256>>>();
    sel_fin2_kernel<<<1, 32>>>();
    tsplit_kernel<<<tg, 256>>>(qkv + 0,  QKV_LD, (size_t)S_*QKV_LD, nullptr, nq, 0, qT0, qT1);
    tsplit_kernel<<<tg, 256>>>(qkv + E_, QKV_LD, (size_t)S_*QKV_LD, nullptr, nk, 4, kT0, kT1);
    mma_nt<<<ge, 256>>>(qT0, qT1, ES, kT0, kT1, ES,
                        nullptr, am0, am1, EE, E_, S_, nullptr, 1.f);        // Am

    // ---- join: Ut needs Tt (B) + Am (A); out needs Ut ----
    cudaStreamWaitEvent(0, evB, 0);
    mma_nt<<<ge, 256>>>(tt0, tt1, EE, am0, am1, EE,
                        nullptr, ut0, ut1, EE, E_, E_, nullptr, 1.f / 32.f); // Ut
    mma_nt<<<dim3(E_/128, S_/128, B_), 256>>>(
        x0, x1, SE, ut0, ut1, EE,
        out, nullptr, nullptr, SE, E_, E_, nullptr, 1.f);                    // out
}